// round 2
// baseline (speedup 1.0000x reference)
#include <cuda_runtime.h>

#define DD       32
#define HID      128
#define NN       4096
#define BB       8
#define NODES    (BB * NN)          // 32768
#define DT_STEP  0.25f
#define N_STEPS  18

// Precomputed per-node constant:  c[net][m][j] = b1[j] + sum_i xi[i] * W1[64+i][j]
// (xi never changes across steps, so this is computed once per call.)
__device__ float g_c[2][(size_t)NODES * HID];   // 2 x 16 MB static scratch

__device__ __forceinline__ float fast_tanh(float x)
{
    float e = __expf(2.0f * x);
    return 1.0f - 2.0f / (e + 1.0f);
}

// ---------------------------------------------------------------------------
// init: fold xi @ W1[64:80] + b1 into g_c for both nets. 128 threads/block,
// one thread per node, 256 blocks.
// ---------------------------------------------------------------------------
__global__ void init_c_kernel(const float* __restrict__ x,
                              const float* __restrict__ W1q, const float* __restrict__ b1q,
                              const float* __restrict__ W1p, const float* __restrict__ b1p)
{
    __shared__ float sW[2][16 * HID];
    __shared__ float sb[2][HID];
    const int tid = threadIdx.x;  // 128
    {
        const float4* s0 = (const float4*)(W1q + 64 * HID);
        const float4* s1 = (const float4*)(W1p + 64 * HID);
        float4* d0 = (float4*)sW[0];
        float4* d1 = (float4*)sW[1];
        #pragma unroll
        for (int k = 0; k < 4; k++) {
            d0[tid + 128 * k] = s0[tid + 128 * k];
            d1[tid + 128 * k] = s1[tid + 128 * k];
        }
        sb[0][tid] = b1q[tid];
        sb[1][tid] = b1p[tid];
    }
    __syncthreads();

    const int m = blockIdx.x * 128 + tid;
    float xi[16];
    #pragma unroll
    for (int k = 0; k < 4; k++) {
        float4 v = *(const float4*)(x + (size_t)m * 80 + 64 + 4 * k);
        xi[4 * k + 0] = v.x; xi[4 * k + 1] = v.y;
        xi[4 * k + 2] = v.z; xi[4 * k + 3] = v.w;
    }

    #pragma unroll
    for (int net = 0; net < 2; net++) {
        for (int jg = 0; jg < 32; jg++) {
            float4 acc = *(const float4*)&sb[net][jg * 4];
            #pragma unroll
            for (int i = 0; i < 16; i++) {
                float4 w = *(const float4*)&sW[net][i * HID + jg * 4];
                acc.x = fmaf(xi[i], w.x, acc.x);
                acc.y = fmaf(xi[i], w.y, acc.y);
                acc.z = fmaf(xi[i], w.z, acc.z);
                acc.w = fmaf(xi[i], w.w, acc.w);
            }
            *(float4*)&g_c[net][(size_t)m * HID + jg * 4] = acc;
        }
    }
}

// ---------------------------------------------------------------------------
// One integrator phase:  dst += dt * ( tanh([z, z_nbr] @ W1[0:64] + c) @ W2 + b2 )
// 64 threads/block = 2 warps; each warp covers 16 nodes x 2 hidden-halves
// (pair lanes l and l+16). 1024 blocks.
// ---------------------------------------------------------------------------
__global__ __launch_bounds__(64, 7)
void phase_kernel(float* __restrict__ state,          // d_out, [NODES][80]
                  const float* __restrict__ tfinal,   // [B]
                  const float* __restrict__ W1,       // [80][128] (rows 0..63 used)
                  const float* __restrict__ W2,       // [128][32]
                  const float* __restrict__ b2,       // [32]
                  const int*   __restrict__ nbrs,     // [NN][4]
                  int net, int read_off, int write_off,
                  float t_base, float dt_max)
{
    __shared__ float sW1[64 * HID];   // 32 KB: W1 rows 0..63
    const int tid = threadIdx.x;      // 64
    {
        const float4* src = (const float4*)W1;
        float4* dst = (float4*)sW1;
        #pragma unroll
        for (int k = 0; k < 32; k++)
            dst[tid + 64 * k] = src[tid + 64 * k];
    }
    __syncthreads();

    const int lane = tid & 31;
    const int jh   = lane >> 4;                           // hidden half: 0 or 1
    const int m    = blockIdx.x * 32 + (tid >> 5) * 16 + (lane & 15);
    const int b    = m >> 12;
    const int n    = m & (NN - 1);

    // ---- gather inputs: in[0:32] = z_self, in[32:64] = mean of 4 neighbours ----
    float in[64];
    const float* zs = state + (size_t)m * 80 + read_off;
    #pragma unroll
    for (int k = 0; k < 8; k++) {
        float4 v = *(const float4*)(zs + 4 * k);
        in[4 * k + 0] = v.x; in[4 * k + 1] = v.y;
        in[4 * k + 2] = v.z; in[4 * k + 3] = v.w;
    }
    const int4 nb = *(const int4*)(nbrs + n * 4);
    const int nbase = b << 12;
    const float* q0 = state + (size_t)(nbase + nb.x) * 80 + read_off;
    const float* q1 = state + (size_t)(nbase + nb.y) * 80 + read_off;
    const float* q2 = state + (size_t)(nbase + nb.z) * 80 + read_off;
    const float* q3 = state + (size_t)(nbase + nb.w) * 80 + read_off;
    #pragma unroll
    for (int k = 0; k < 8; k++) {
        float4 a0 = *(const float4*)(q0 + 4 * k);
        float4 a1 = *(const float4*)(q1 + 4 * k);
        float4 a2 = *(const float4*)(q2 + 4 * k);
        float4 a3 = *(const float4*)(q3 + 4 * k);
        in[32 + 4 * k + 0] = 0.25f * ((a0.x + a1.x) + (a2.x + a3.x));
        in[32 + 4 * k + 1] = 0.25f * ((a0.y + a1.y) + (a2.y + a3.y));
        in[32 + 4 * k + 2] = 0.25f * ((a0.z + a1.z) + (a2.z + a3.z));
        in[32 + 4 * k + 3] = 0.25f * ((a0.w + a1.w) + (a2.w + a3.w));
    }

    // ---- output accumulators (half 0 seeds b2, half 1 seeds 0) ----
    float out[32];
    if (jh == 0) {
        #pragma unroll
        for (int k = 0; k < 8; k++) {
            float4 v = __ldg((const float4*)(b2 + 4 * k));
            out[4 * k + 0] = v.x; out[4 * k + 1] = v.y;
            out[4 * k + 2] = v.z; out[4 * k + 3] = v.w;
        }
    } else {
        #pragma unroll
        for (int d = 0; d < 32; d++) out[d] = 0.0f;
    }

    const float* cb  = g_c[net] + (size_t)m * HID + jh * 64;
    const float* W2h = W2 + jh * 64 * 32;

    // ---- main loop: 16 groups of 4 hidden units ----
    #pragma unroll 1
    for (int jg = 0; jg < 16; jg++) {
        float4 acc = *(const float4*)(cb + jg * 4);
        const float* wc = sW1 + jh * 64 + jg * 4;
        #pragma unroll
        for (int i = 0; i < 64; i++) {
            float4 w = *(const float4*)(wc + i * HID);
            acc.x = fmaf(in[i], w.x, acc.x);
            acc.y = fmaf(in[i], w.y, acc.y);
            acc.z = fmaf(in[i], w.z, acc.z);
            acc.w = fmaf(in[i], w.w, acc.w);
        }
        const float h0 = fast_tanh(acc.x);
        const float h1 = fast_tanh(acc.y);
        const float h2 = fast_tanh(acc.z);
        const float h3 = fast_tanh(acc.w);

        const float* w2r = W2h + jg * 4 * 32;
        #pragma unroll
        for (int d4 = 0; d4 < 8; d4++) {
            float4 w0 = __ldg((const float4*)(w2r + 0 * 32 + 4 * d4));
            float4 w1 = __ldg((const float4*)(w2r + 1 * 32 + 4 * d4));
            float4 w2v = __ldg((const float4*)(w2r + 2 * 32 + 4 * d4));
            float4 w3 = __ldg((const float4*)(w2r + 3 * 32 + 4 * d4));
            out[4 * d4 + 0] = fmaf(h3, w3.x, fmaf(h2, w2v.x, fmaf(h1, w1.x, fmaf(h0, w0.x, out[4 * d4 + 0]))));
            out[4 * d4 + 1] = fmaf(h3, w3.y, fmaf(h2, w2v.y, fmaf(h1, w1.y, fmaf(h0, w0.y, out[4 * d4 + 1]))));
            out[4 * d4 + 2] = fmaf(h3, w3.z, fmaf(h2, w2v.z, fmaf(h1, w1.z, fmaf(h0, w0.z, out[4 * d4 + 2]))));
            out[4 * d4 + 3] = fmaf(h3, w3.w, fmaf(h2, w2v.w, fmaf(h1, w1.w, fmaf(h0, w0.w, out[4 * d4 + 3]))));
        }
    }

    // ---- combine the two hidden-halves (lanes l and l+16) ----
    #pragma unroll
    for (int d = 0; d < 32; d++)
        out[d] += __shfl_down_sync(0xffffffffu, out[d], 16);

    if (jh == 0) {
        const float tf = __ldg(tfinal + b);
        const float dt = fminf(fmaxf(tf - t_base, 0.0f), dt_max);
        float* w = state + (size_t)m * 80 + write_off;
        #pragma unroll
        for (int d4 = 0; d4 < 8; d4++) {
            float4 v = *(const float4*)(w + 4 * d4);
            v.x = fmaf(dt, out[4 * d4 + 0], v.x);
            v.y = fmaf(dt, out[4 * d4 + 1], v.y);
            v.z = fmaf(dt, out[4 * d4 + 2], v.z);
            v.w = fmaf(dt, out[4 * d4 + 3], v.w);
            *(float4*)(w + 4 * d4) = v;
        }
    }
}

// ---------------------------------------------------------------------------
extern "C" void kernel_launch(void* const* d_in, const int* in_sizes, int n_in,
                              void* d_out, int out_size)
{
    const float* x   = (const float*)d_in[0];
    const float* tfi = (const float*)d_in[1];
    const float* W1q = (const float*)d_in[2];
    const float* b1q = (const float*)d_in[3];
    const float* W2q = (const float*)d_in[4];
    const float* b2q = (const float*)d_in[5];
    const float* W1p = (const float*)d_in[6];
    const float* b1p = (const float*)d_in[7];
    const float* W2p = (const float*)d_in[8];
    const float* b2p = (const float*)d_in[9];
    const int*  nbrs = (const int*)d_in[10];
    float* out = (float*)d_out;

    // state (q, p, xi interleaved) lives directly in d_out
    cudaMemcpyAsync(out, x, (size_t)NODES * 80 * sizeof(float),
                    cudaMemcpyDeviceToDevice);
    init_c_kernel<<<NODES / 128, 128>>>(x, W1q, b1q, W1p, b1p);

    float tq = 0.0f, tp = 0.0f;
    for (int k = 0; k < N_STEPS; k++) {
        const float rho = (k == 0) ? 0.5f : 1.0f;
        // q-update: reads p (offset 32), writes q (offset 0)
        phase_kernel<<<1024, 64>>>(out, tfi, W1q, W2q, b2q, nbrs,
                                   0, DD, 0, tq, rho * DT_STEP);
        tq += rho * DT_STEP;
        // p-update: reads q (offset 0), writes p (offset 32)
        phase_kernel<<<1024, 64>>>(out, tfi, W1p, W2p, b2p, nbrs,
                                   1, 0, DD, tp, DT_STEP);
        tp += DT_STEP;
    }
}

// round 4
// speedup vs baseline: 2.5026x; 2.5026x over previous
#include <cuda_runtime.h>

#define DD       32
#define HID      128
#define NN       4096
#define BB       8
#define NODES    (BB * NN)          // 32768
#define DT_STEP  0.25f
#define N_STEPS  18
#define TM       32                 // nodes per block
#define XS       36                 // padded smem row stride (floats), 16B-aligned

// Transposed precomputed constant: g_cT[net][j * NODES + m] = b1[j] + sum_i xi[m][i] * W1[64+i][j]
__device__ float g_cT[2][(size_t)HID * NODES];   // 2 x 16 MB static scratch

__device__ __forceinline__ float fast_tanh(float x)
{
    float e = __expf(2.0f * x);
    return 1.0f - 2.0f / (e + 1.0f);
}

// ---------------------------------------------------------------------------
// init: fold xi @ W1[64:80] + b1 into g_cT (transposed) for both nets.
// 128 threads/block, one thread per node, 256 blocks. Writes are coalesced
// (consecutive threads -> consecutive m within a j-row).
// ---------------------------------------------------------------------------
__global__ void init_c_kernel(const float* __restrict__ x,
                              const float* __restrict__ W1q, const float* __restrict__ b1q,
                              const float* __restrict__ W1p, const float* __restrict__ b1p)
{
    __shared__ float sW[2][16 * HID];
    __shared__ float sb[2][HID];
    const int tid = threadIdx.x;  // 128
    {
        const float4* s0 = (const float4*)(W1q + 64 * HID);
        const float4* s1 = (const float4*)(W1p + 64 * HID);
        float4* d0 = (float4*)sW[0];
        float4* d1 = (float4*)sW[1];
        #pragma unroll
        for (int k = 0; k < 4; k++) {
            d0[tid + 128 * k] = s0[tid + 128 * k];
            d1[tid + 128 * k] = s1[tid + 128 * k];
        }
        sb[0][tid] = b1q[tid];
        sb[1][tid] = b1p[tid];
    }
    __syncthreads();

    const int m = blockIdx.x * 128 + tid;
    float xi[16];
    #pragma unroll
    for (int k = 0; k < 4; k++) {
        float4 v = *(const float4*)(x + (size_t)m * 80 + 64 + 4 * k);
        xi[4 * k + 0] = v.x; xi[4 * k + 1] = v.y;
        xi[4 * k + 2] = v.z; xi[4 * k + 3] = v.w;
    }

    #pragma unroll
    for (int net = 0; net < 2; net++) {
        for (int jg = 0; jg < 32; jg++) {
            float4 acc = *(const float4*)&sb[net][jg * 4];
            #pragma unroll
            for (int i = 0; i < 16; i++) {
                float4 w = *(const float4*)&sW[net][i * HID + jg * 4];
                acc.x = fmaf(xi[i], w.x, acc.x);
                acc.y = fmaf(xi[i], w.y, acc.y);
                acc.z = fmaf(xi[i], w.z, acc.z);
                acc.w = fmaf(xi[i], w.w, acc.w);
            }
            g_cT[net][(size_t)(jg * 4 + 0) * NODES + m] = acc.x;
            g_cT[net][(size_t)(jg * 4 + 1) * NODES + m] = acc.y;
            g_cT[net][(size_t)(jg * 4 + 2) * NODES + m] = acc.z;
            g_cT[net][(size_t)(jg * 4 + 3) * NODES + m] = acc.w;
        }
    }
}

// ---------------------------------------------------------------------------
// One integrator phase, smem-tiled:
//   dst += dt * ( tanh([z, z_nbr] @ W1[0:64] + c) @ W2 + b2 )
// 128 threads/block, TM=32 nodes/block, 1024 blocks, 4 blocks/SM.
// dyn smem: sW1 (64x128 = 32KB) + sU (128x36 = 18KB union of xT then h).
// ---------------------------------------------------------------------------
__global__ __launch_bounds__(128, 4)
void phase2_kernel(float* __restrict__ state,          // d_out, [NODES][80]
                   const float* __restrict__ tfinal,   // [B]
                   const float* __restrict__ W1,       // [80][128] (rows 0..63 used)
                   const float* __restrict__ W2,       // [128][32]
                   const float* __restrict__ b2,       // [32]
                   const int*   __restrict__ nbrs,     // [NN][4]
                   int net, int read_off, int write_off,
                   float t_base, float dt_max)
{
    extern __shared__ float sm[];
    float* sW1 = sm;              // 64*128 floats = 32KB
    float* sU  = sm + 64 * HID;   // 128*XS floats: xT rows 0..63, then h rows 0..127

    const int tid = threadIdx.x;          // 128
    const int m0  = blockIdx.x * TM;
    const float* cT = g_cT[net];

    // ---- load W1 rows 0..63 into smem ----
    {
        const float4* src = (const float4*)W1;
        float4* dst = (float4*)sW1;
        #pragma unroll
        for (int k = 0; k < 16; k++)
            dst[tid + 128 * k] = src[tid + 128 * k];
    }

    // ---- gather inputs, transposed: sU[i][n], i 0..31 self z, 32..63 nbr mean ----
    {
        const int n = tid >> 2;           // local node 0..31
        const int p = tid & 3;            // 0..3
        const int m = m0 + n;
        const int b = m >> 12;
        const int ng = m & (NN - 1);
        const int4 nb = *(const int4*)(nbrs + ng * 4);
        const int nbase = b << 12;
        #pragma unroll
        for (int k = 0; k < 4; k++) {
            const int d0 = 16 * k + 4 * p;     // multiples of 4, covers 0..60
            float4 v;
            if (d0 < 32) {
                v = *(const float4*)(state + (size_t)m * 80 + read_off + d0);
            } else {
                const int dd = d0 - 32;
                float4 a0 = *(const float4*)(state + (size_t)(nbase + nb.x) * 80 + read_off + dd);
                float4 a1 = *(const float4*)(state + (size_t)(nbase + nb.y) * 80 + read_off + dd);
                float4 a2 = *(const float4*)(state + (size_t)(nbase + nb.z) * 80 + read_off + dd);
                float4 a3 = *(const float4*)(state + (size_t)(nbase + nb.w) * 80 + read_off + dd);
                v.x = 0.25f * ((a0.x + a1.x) + (a2.x + a3.x));
                v.y = 0.25f * ((a0.y + a1.y) + (a2.y + a3.y));
                v.z = 0.25f * ((a0.z + a1.z) + (a2.z + a3.z));
                v.w = 0.25f * ((a0.w + a1.w) + (a2.w + a3.w));
            }
            sU[(d0 + 0) * XS + n] = v.x;
            sU[(d0 + 1) * XS + n] = v.y;
            sU[(d0 + 2) * XS + n] = v.z;
            sU[(d0 + 3) * XS + n] = v.w;
        }
    }
    __syncthreads();

    // ---- GEMM1: acc[4 hidden][8 nodes] per thread ----
    const int hgr = tid >> 2;     // 0..31 : hidden group (4 units)
    const int ngr = tid & 3;      // 0..3  : node group (8 nodes)
    float acc[4][8];
    #pragma unroll
    for (int jj = 0; jj < 4; jj++) {
        const size_t jrow = (size_t)(hgr * 4 + jj) * NODES + m0 + ngr * 8;
        float4 c0 = *(const float4*)(cT + jrow);
        float4 c1 = *(const float4*)(cT + jrow + 4);
        acc[jj][0] = c0.x; acc[jj][1] = c0.y; acc[jj][2] = c0.z; acc[jj][3] = c0.w;
        acc[jj][4] = c1.x; acc[jj][5] = c1.y; acc[jj][6] = c1.z; acc[jj][7] = c1.w;
    }

    #pragma unroll 4
    for (int i = 0; i < 64; i++) {
        float4 w  = *(const float4*)(sW1 + i * HID + hgr * 4);
        float4 xa = *(const float4*)(sU + i * XS + ngr * 8);
        float4 xb = *(const float4*)(sU + i * XS + ngr * 8 + 4);
        const float wv[4] = {w.x, w.y, w.z, w.w};
        const float xv[8] = {xa.x, xa.y, xa.z, xa.w, xb.x, xb.y, xb.z, xb.w};
        #pragma unroll
        for (int jj = 0; jj < 4; jj++)
            #pragma unroll
            for (int nn = 0; nn < 8; nn++)
                acc[jj][nn] = fmaf(wv[jj], xv[nn], acc[jj][nn]);
    }

    __syncthreads();   // all reads of xT done; sU may now be overwritten with h

    // ---- tanh + store h transposed: sU[j][n] ----
    #pragma unroll
    for (int jj = 0; jj < 4; jj++) {
        const int j = hgr * 4 + jj;
        float4 h0, h1;
        h0.x = fast_tanh(acc[jj][0]); h0.y = fast_tanh(acc[jj][1]);
        h0.z = fast_tanh(acc[jj][2]); h0.w = fast_tanh(acc[jj][3]);
        h1.x = fast_tanh(acc[jj][4]); h1.y = fast_tanh(acc[jj][5]);
        h1.z = fast_tanh(acc[jj][6]); h1.w = fast_tanh(acc[jj][7]);
        *(float4*)(sU + j * XS + ngr * 8)     = h0;
        *(float4*)(sU + j * XS + ngr * 8 + 4) = h1;
    }
    __syncthreads();

    // ---- GEMM2: out[8 nodes] per thread, thread owns output dim d ----
    const int d   = tid >> 2;     // 0..31
    const int ng2 = tid & 3;      // 0..3
    float out[8];
    {
        const float bb = __ldg(b2 + d);
        #pragma unroll
        for (int nn = 0; nn < 8; nn++) out[nn] = bb;
    }
    #pragma unroll 4
    for (int j = 0; j < 128; j++) {
        const float w2 = __ldg(W2 + j * 32 + d);
        float4 h0 = *(const float4*)(sU + j * XS + ng2 * 8);
        float4 h1 = *(const float4*)(sU + j * XS + ng2 * 8 + 4);
        out[0] = fmaf(w2, h0.x, out[0]);
        out[1] = fmaf(w2, h0.y, out[1]);
        out[2] = fmaf(w2, h0.z, out[2]);
        out[3] = fmaf(w2, h0.w, out[3]);
        out[4] = fmaf(w2, h1.x, out[4]);
        out[5] = fmaf(w2, h1.y, out[5]);
        out[6] = fmaf(w2, h1.z, out[6]);
        out[7] = fmaf(w2, h1.w, out[7]);
    }

    // ---- scaled accumulate into state ----
    const int b = m0 >> 12;
    const float tf = __ldg(tfinal + b);
    const float dt = fminf(fmaxf(tf - t_base, 0.0f), dt_max);
    #pragma unroll
    for (int nn = 0; nn < 8; nn++) {
        const int m = m0 + ng2 * 8 + nn;
        float* pp = state + (size_t)m * 80 + write_off + d;
        *pp = fmaf(dt, out[nn], *pp);
    }
}

// ---------------------------------------------------------------------------
extern "C" void kernel_launch(void* const* d_in, const int* in_sizes, int n_in,
                              void* d_out, int out_size)
{
    const float* x   = (const float*)d_in[0];
    const float* tfi = (const float*)d_in[1];
    const float* W1q = (const float*)d_in[2];
    const float* b1q = (const float*)d_in[3];
    const float* W2q = (const float*)d_in[4];
    const float* b2q = (const float*)d_in[5];
    const float* W1p = (const float*)d_in[6];
    const float* b1p = (const float*)d_in[7];
    const float* W2p = (const float*)d_in[8];
    const float* b2p = (const float*)d_in[9];
    const int*  nbrs = (const int*)d_in[10];
    float* out = (float*)d_out;

    const int smem_bytes = (64 * HID + HID * XS) * (int)sizeof(float);  // 50 KB
    cudaFuncSetAttribute(phase2_kernel,
                         cudaFuncAttributeMaxDynamicSharedMemorySize, smem_bytes);

    // state (q, p, xi interleaved) lives directly in d_out
    cudaMemcpyAsync(out, x, (size_t)NODES * 80 * sizeof(float),
                    cudaMemcpyDeviceToDevice);
    init_c_kernel<<<NODES / 128, 128>>>(x, W1q, b1q, W1p, b1p);

    float tq = 0.0f, tp = 0.0f;
    for (int k = 0; k < N_STEPS; k++) {
        const float rho = (k == 0) ? 0.5f : 1.0f;
        // q-update: reads p (offset 32), writes q (offset 0)
        phase2_kernel<<<NODES / TM, 128, smem_bytes>>>(out, tfi, W1q, W2q, b2q, nbrs,
                                                       0, DD, 0, tq, rho * DT_STEP);
        tq += rho * DT_STEP;
        // p-update: reads q (offset 0), writes p (offset 32)
        phase2_kernel<<<NODES / TM, 128, smem_bytes>>>(out, tfi, W1p, W2p, b2p, nbrs,
                                                       1, 0, DD, tp, DT_STEP);
        tp += DT_STEP;
    }
}

// round 6
// speedup vs baseline: 3.3867x; 1.3533x over previous
#include <cuda_runtime.h>
#include <cuda_bf16.h>
#include <cstdint>

#define DD       32
#define HID      128
#define NN       4096
#define NODES    32768
#define DT_STEP  0.25f
#define N_STEPS  18
#define TMN      128                 // nodes (M) per block
#define NBLK     (NODES / TMN)       // 256
#define NTHR     512

#define SK1      264                 // A1/B1/A2 row stride in bf16 elems (K=256 + 8 pad)
#define SKB2     392                 // B2 row stride (K=384 + 8 pad)

// smem byte offsets
#define SM_A     0                                // A1 then A2(h) union: 128*264*2 = 67584
#define SM_B1    67584                            // B1: 128*264*2 = 67584
#define SM_B2    (SM_B1 + 67584)                  // B2: 32*392*2 = 25088
#define SM_TOTAL (SM_B2 + 25088)                  // 160256 B

// Prebuilt bf16 weight images (row-major padded; built once per launch)
__device__ unsigned short g_B1[2][128 * SK1];
__device__ unsigned short g_B2[2][32 * SKB2];

// ---------------------------------------------------------------------------
__device__ __forceinline__ uint32_t smem_u32(const void* p) {
    uint32_t a;
    asm("{ .reg .u64 t; cvta.to.shared.u64 t, %1; cvt.u32.u64 %0, t; }" : "=r"(a) : "l"(p));
    return a;
}
__device__ __forceinline__ void ldsm_x4(uint32_t (&r)[4], uint32_t addr) {
    asm volatile("ldmatrix.sync.aligned.m8n8.x4.shared.b16 {%0,%1,%2,%3}, [%4];"
        : "=r"(r[0]), "=r"(r[1]), "=r"(r[2]), "=r"(r[3]) : "r"(addr));
}
__device__ __forceinline__ void ldsm_x2(uint32_t (&r)[2], uint32_t addr) {
    asm volatile("ldmatrix.sync.aligned.m8n8.x2.shared.b16 {%0,%1}, [%2];"
        : "=r"(r[0]), "=r"(r[1]) : "r"(addr));
}
__device__ __forceinline__ void mma16816(float (&c)[4], const uint32_t (&a)[4],
                                         uint32_t b0, uint32_t b1) {
    asm volatile("mma.sync.aligned.m16n8k16.row.col.f32.bf16.bf16.f32 "
        "{%0,%1,%2,%3}, {%4,%5,%6,%7}, {%8,%9}, {%0,%1,%2,%3};"
        : "+f"(c[0]), "+f"(c[1]), "+f"(c[2]), "+f"(c[3])
        : "r"(a[0]), "r"(a[1]), "r"(a[2]), "r"(a[3]), "r"(b0), "r"(b1));
}
__device__ __forceinline__ uint32_t bfhi2(float a, float b) {
    return (uint32_t)__bfloat16_as_ushort(__float2bfloat16_rn(a))
         | ((uint32_t)__bfloat16_as_ushort(__float2bfloat16_rn(b)) << 16);
}
__device__ __forceinline__ float bfres(float a) {
    return a - __bfloat162float(__float2bfloat16_rn(a));
}
__device__ __forceinline__ float fast_tanh(float x) {
    float e = __expf(2.0f * x);
    return 1.0f - 2.0f / (e + 1.0f);
}

// ---------------------------------------------------------------------------
// Build bf16 weight images.  grid = 2 (net), 256 threads.
// B1[n][k], K=256:  k0..63   hi(W1[k][n])         (pairs x_hi)
//                   k64..127 hi(W1[k-64][n])      (pairs x_lo)
//                   k128..191 lo(W1[k-128][n])    (pairs x_hi)
//                   k192..207 hi(W1[64+kk][n])    (xi_hi)
//                   k208..223 hi(W1[64+kk-16][n]) (xi_lo)
//                   k224..239 lo(W1[64+kk-32][n]) (xi_hi)
//                   k240 hi(b1[n]); k241 lo(b1[n]); 242..255 zero
// B2[n][k], K=384:  k0..127 hi(W2[k][n]); k128..255 hi(W2[k-128][n]);
//                   k256..383 lo(W2[k-256][n])
// ---------------------------------------------------------------------------
__global__ void prep_weights(const float* __restrict__ W1q, const float* __restrict__ b1q,
                             const float* __restrict__ W2q,
                             const float* __restrict__ W1p, const float* __restrict__ b1p,
                             const float* __restrict__ W2p)
{
    const int net = blockIdx.x;
    const float* W1 = net ? W1p : W1q;
    const float* b1 = net ? b1p : b1q;
    const float* W2 = net ? W2p : W2q;

    for (int idx = threadIdx.x; idx < 128 * 256; idx += blockDim.x) {
        const int n = idx & 127, k = idx >> 7;
        const int seg = k >> 6, kk = k & 63;
        float v = 0.0f; int lo = 0;
        if (seg < 2)            { v = W1[kk * HID + n]; }
        else if (seg == 2)      { v = W1[kk * HID + n]; lo = 1; }
        else {
            if (kk < 32)        { v = W1[(64 + (kk & 15)) * HID + n]; }
            else if (kk < 48)   { v = W1[(64 + kk - 32) * HID + n]; lo = 1; }
            else if (kk == 48)  { v = b1[n]; }
            else if (kk == 49)  { v = b1[n]; lo = 1; }
        }
        const float w = lo ? bfres(v) : v;
        g_B1[net][n * SK1 + k] = __bfloat16_as_ushort(__float2bfloat16_rn(w));
    }
    for (int idx = threadIdx.x; idx < 32 * 384; idx += blockDim.x) {
        const int n = idx / 384, k = idx % 384;
        const int seg = k >> 7, kk = k & 127;
        const float v = W2[kk * 32 + n];
        const float w = (seg == 2) ? bfres(v) : v;
        g_B2[net][n * SKB2 + k] = __bfloat16_as_ushort(__float2bfloat16_rn(w));
    }
}

// ---------------------------------------------------------------------------
// One integrator phase via warp-level bf16 HMMA.  512 threads, 128 nodes/block.
// ---------------------------------------------------------------------------
__global__ __launch_bounds__(NTHR, 1)
void tc_phase(float* __restrict__ state, const float* __restrict__ tfinal,
              const float* __restrict__ b2, const int* __restrict__ nbrs,
              int net, int roff, int woff, float t_base, float dt_max)
{
    extern __shared__ unsigned char sm[];
    const uint32_t sbase = smem_u32(sm);
    const int tid = threadIdx.x;
    const int wid = tid >> 5;
    const int lane = tid & 31;
    const int m0 = blockIdx.x * TMN;

    // ---- copy weight images to smem ----
    {
        const float4* s1 = (const float4*)g_B1[net];
        float4* d1 = (float4*)(sm + SM_B1);
        for (int i = tid; i < 67584 / 16; i += NTHR) d1[i] = s1[i];
        const float4* s2 = (const float4*)g_B2[net];
        float4* d2 = (float4*)(sm + SM_B2);
        for (int i = tid; i < 25088 / 16; i += NTHR) d2[i] = s2[i];
    }

    // ---- build A1: gather + bf16 split.  4 threads per node row ----
    {
        const int r = tid >> 2, part = tid & 3;   // part 0/1: self halves; 2/3: nbr halves
        const int m = m0 + r;
        float z[16];
        if (part < 2) {
            const float* p = state + (size_t)m * 80 + roff + part * 16;
            #pragma unroll
            for (int i = 0; i < 4; i++) {
                float4 v = ((const float4*)p)[i];
                z[4*i] = v.x; z[4*i+1] = v.y; z[4*i+2] = v.z; z[4*i+3] = v.w;
            }
        } else {
            const int b = m >> 12, n = m & (NN - 1);
            const int4 nb = *(const int4*)(nbrs + n * 4);
            const int nbase = b << 12;
            const int off = roff + (part - 2) * 16;
            const float* p0 = state + (size_t)(nbase + nb.x) * 80 + off;
            const float* p1 = state + (size_t)(nbase + nb.y) * 80 + off;
            const float* p2 = state + (size_t)(nbase + nb.z) * 80 + off;
            const float* p3 = state + (size_t)(nbase + nb.w) * 80 + off;
            #pragma unroll
            for (int i = 0; i < 4; i++) {
                float4 a0 = ((const float4*)p0)[i], a1 = ((const float4*)p1)[i];
                float4 a2 = ((const float4*)p2)[i], a3 = ((const float4*)p3)[i];
                z[4*i]   = 0.25f * ((a0.x + a1.x) + (a2.x + a3.x));
                z[4*i+1] = 0.25f * ((a0.y + a1.y) + (a2.y + a3.y));
                z[4*i+2] = 0.25f * ((a0.z + a1.z) + (a2.z + a3.z));
                z[4*i+3] = 0.25f * ((a0.w + a1.w) + (a2.w + a3.w));
            }
        }
        unsigned char* A = sm + SM_A;
        const int c0 = part * 16;                 // cols 0..63: [self(32) | nbr(32)]
        #pragma unroll
        for (int i = 0; i < 16; i += 2) {
            const uint32_t uh = bfhi2(z[i], z[i+1]);
            const uint32_t ul = bfhi2(bfres(z[i]), bfres(z[i+1]));
            *(uint32_t*)(A + (r * SK1 + c0 + i)       * 2) = uh;
            *(uint32_t*)(A + (r * SK1 + c0 + 64 + i)  * 2) = ul;
            *(uint32_t*)(A + (r * SK1 + c0 + 128 + i) * 2) = uh;
        }
        if (part == 0) {   // xi block + constants
            float xi[16];
            const float* p = state + (size_t)m * 80 + 64;
            #pragma unroll
            for (int i = 0; i < 4; i++) {
                float4 v = ((const float4*)p)[i];
                xi[4*i] = v.x; xi[4*i+1] = v.y; xi[4*i+2] = v.z; xi[4*i+3] = v.w;
            }
            #pragma unroll
            for (int i = 0; i < 16; i += 2) {
                const uint32_t uh = bfhi2(xi[i], xi[i+1]);
                const uint32_t ul = bfhi2(bfres(xi[i]), bfres(xi[i+1]));
                *(uint32_t*)(A + (r * SK1 + 192 + i) * 2) = uh;
                *(uint32_t*)(A + (r * SK1 + 208 + i) * 2) = ul;
                *(uint32_t*)(A + (r * SK1 + 224 + i) * 2) = uh;
            }
            *(uint32_t*)(A + (r * SK1 + 240) * 2) = 0x3F803F80u;   // (1.0, 1.0)
            #pragma unroll
            for (int c = 242; c < 256; c += 2)
                *(uint32_t*)(A + (r * SK1 + c) * 2) = 0u;
        }
    }
    __syncthreads();

    // ---- per-lane ldmatrix address components ----
    const int a_row  = lane & 15;            // + tile row base
    const int a_koff = (lane >> 4) << 3;
    const int b_nofs = (lane & 7) + ((lane >> 4) << 3);
    const int b_koff = ((lane >> 3) & 1) << 3;

    // ---- GEMM1: C1[128x128] = A1[128x256] @ B1[128x256]^T ----
    const int wm = (wid >> 2) * 32;          // row tile base
    const int wn = (wid & 3) * 32;           // col tile base
    float acc[2][4][4];
    #pragma unroll
    for (int mi = 0; mi < 2; mi++)
        #pragma unroll
        for (int nj = 0; nj < 4; nj++)
            #pragma unroll
            for (int e = 0; e < 4; e++) acc[mi][nj][e] = 0.0f;

    {
        const uint32_t aBase = sbase + SM_A  + (uint32_t)((wm + a_row) * SK1 + a_koff) * 2;
        const uint32_t bBase = sbase + SM_B1 + (uint32_t)((wn + b_nofs) * SK1 + b_koff) * 2;
        #pragma unroll 4
        for (int ks = 0; ks < 16; ks++) {
            uint32_t af[2][4], bf[2][4];
            ldsm_x4(af[0], aBase + ks * 32);
            ldsm_x4(af[1], aBase + ks * 32 + 16 * SK1 * 2);
            ldsm_x4(bf[0], bBase + ks * 32);
            ldsm_x4(bf[1], bBase + ks * 32 + 16 * SK1 * 2);
            #pragma unroll
            for (int mi = 0; mi < 2; mi++) {
                mma16816(acc[mi][0], af[mi], bf[0][0], bf[0][1]);
                mma16816(acc[mi][1], af[mi], bf[0][2], bf[0][3]);
                mma16816(acc[mi][2], af[mi], bf[1][0], bf[1][1]);
                mma16816(acc[mi][3], af[mi], bf[1][2], bf[1][3]);
            }
        }
    }
    __syncthreads();   // all warps done reading A1/B1; A-space may be rewritten

    // ---- tanh epilogue: h = tanh(C1); store h_hi at k=col, h_lo at k=128+col ----
    {
        unsigned char* A = sm + SM_A;
        const int rb = wm + (lane >> 2);
        const int cb = wn + (lane & 3) * 2;
        #pragma unroll
        for (int mi = 0; mi < 2; mi++) {
            #pragma unroll
            for (int nj = 0; nj < 4; nj++) {
                const int c = cb + nj * 8;
                #pragma unroll
                for (int hh = 0; hh < 2; hh++) {      // row, row+8
                    const int r = rb + mi * 16 + hh * 8;
                    const float t0 = fast_tanh(acc[mi][nj][hh * 2 + 0]);
                    const float t1 = fast_tanh(acc[mi][nj][hh * 2 + 1]);
                    *(uint32_t*)(A + (r * SK1 + c)       * 2) = bfhi2(t0, t1);
                    *(uint32_t*)(A + (r * SK1 + 128 + c) * 2) = bfhi2(bfres(t0), bfres(t1));
                }
            }
        }
    }
    __syncthreads();

    // ---- GEMM2: C2[128x32] = h_hi@W2_hi + h_lo@W2_hi + h_hi@W2_lo ----
    const int wn2 = (wid & 3) * 8;
    float acc2[2][4];
    #pragma unroll
    for (int mi = 0; mi < 2; mi++)
        #pragma unroll
        for (int e = 0; e < 4; e++) acc2[mi][e] = 0.0f;

    {
        const int l = lane & 15;
        const uint32_t aBase = sbase + SM_A  + (uint32_t)((wm + a_row) * SK1 + a_koff) * 2;
        const uint32_t bBase = sbase + SM_B2
            + (uint32_t)((wn2 + (l & 7)) * SKB2 + (((l >> 3) & 1) << 3)) * 2;
        #pragma unroll 4
        for (int ks = 0; ks < 24; ks++) {
            const int ka = (ks < 16) ? ks * 16 : (ks - 16) * 16;   // reread h_hi
            uint32_t af[2], al[2][4], bf[2];
            ldsm_x4(al[0], aBase + ka * 2);
            ldsm_x4(al[1], aBase + ka * 2 + 16 * SK1 * 2);
            ldsm_x2(bf, bBase + ks * 32);
            mma16816(acc2[0], al[0], bf[0], bf[1]);
            mma16816(acc2[1], al[1], bf[0], bf[1]);
            (void)af;
        }
    }

    // ---- final epilogue: state += dt * (C2 + b2) ----
    {
        const float tf = __ldg(tfinal + (m0 >> 12));
        const float dt = fminf(fmaxf(tf - t_base, 0.0f), dt_max);
        const int c0 = wn2 + (lane & 3) * 2;
        const float b2v0 = __ldg(b2 + c0);
        const float b2v1 = __ldg(b2 + c0 + 1);
        #pragma unroll
        for (int mi = 0; mi < 2; mi++) {
            const int r0 = m0 + wm + mi * 16 + (lane >> 2);
            float* p0 = state + (size_t)r0 * 80 + woff + c0;
            p0[0] = fmaf(dt, acc2[mi][0] + b2v0, p0[0]);
            p0[1] = fmaf(dt, acc2[mi][1] + b2v1, p0[1]);
            float* p1 = state + (size_t)(r0 + 8) * 80 + woff + c0;
            p1[0] = fmaf(dt, acc2[mi][2] + b2v0, p1[0]);
            p1[1] = fmaf(dt, acc2[mi][3] + b2v1, p1[1]);
        }
    }
}

// ---------------------------------------------------------------------------
extern "C" void kernel_launch(void* const* d_in, const int* in_sizes, int n_in,
                              void* d_out, int out_size)
{
    const float* x   = (const float*)d_in[0];
    const float* tfi = (const float*)d_in[1];
    const float* W1q = (const float*)d_in[2];
    const float* b1q = (const float*)d_in[3];
    const float* W2q = (const float*)d_in[4];
    const float* b2q = (const float*)d_in[5];
    const float* W1p = (const float*)d_in[6];
    const float* b1p = (const float*)d_in[7];
    const float* W2p = (const float*)d_in[8];
    const float* b2p = (const float*)d_in[9];
    const int*  nbrs = (const int*)d_in[10];
    float* out = (float*)d_out;

    cudaFuncSetAttribute(tc_phase, cudaFuncAttributeMaxDynamicSharedMemorySize, SM_TOTAL);

    cudaMemcpyAsync(out, x, (size_t)NODES * 80 * sizeof(float),
                    cudaMemcpyDeviceToDevice);
    prep_weights<<<2, 256>>>(W1q, b1q, W2q, W1p, b1p, W2p);

    float tq = 0.0f, tp = 0.0f;
    for (int k = 0; k < N_STEPS; k++) {
        const float rho = (k == 0) ? 0.5f : 1.0f;
        // q-update: reads p (offset 32), writes q (offset 0)
        tc_phase<<<NBLK, NTHR, SM_TOTAL>>>(out, tfi, b2q, nbrs, 0, DD, 0, tq, rho * DT_STEP);
        tq += rho * DT_STEP;
        // p-update: reads q (offset 0), writes p (offset 32)
        tc_phase<<<NBLK, NTHR, SM_TOTAL>>>(out, tfi, b2p, nbrs, 1, 0, DD, tp, DT_STEP);
        tp += DT_STEP;
    }
}

// round 7
// speedup vs baseline: 3.6612x; 1.0811x over previous
#include <cuda_runtime.h>
#include <cuda_bf16.h>
#include <cstdint>

#define NN       4096
#define NODES    32768
#define DT_STEP  0.25f
#define N_STEPS  18
#define TMN      128                 // nodes (M) per block
#define NBLK     (NODES / TMN)       // 256
#define NTHR     512
#define POFF     32                  // p-field offset within 80-float node record

#define SA1      136                 // A1 row stride (elems): 128 K + 8 pad
#define SH       272                 // h row stride (elems): hi at col 0, lo at col 136
#define SM_A1    0
#define SM_H     (128 * SA1 * 2)                  // 34816
#define SM_TOTAL (SM_H + 128 * SH * 2)            // 104448 bytes

// Fragment-ordered constants, built once per launch.
// C1 init: b1[n] + xi[m] @ W1[64:80][n], in mma accumulator fragment order.
__device__ float g_C1f[2][NBLK][16][2][4][32][4];          // 32 MB
// B1 fragments: [net][wn/32][f(0..3 hi,4..7 lo)][half][lane] (ldmatrix x4 regs)
__device__ uint4 g_B1f[2][4][8][2][32];
// B2 fragments: [net][wn2/8][f(0..7 hi,8..15 lo)][lane] (ldmatrix x2 regs)
__device__ uint2 g_B2f[2][4][16][32];

// ---------------------------------------------------------------------------
__device__ __forceinline__ uint32_t smem_u32(const void* p) {
    uint32_t a;
    asm("{ .reg .u64 t; cvta.to.shared.u64 t, %1; cvt.u32.u64 %0, t; }" : "=r"(a) : "l"(p));
    return a;
}
__device__ __forceinline__ void ldsm_x4(uint32_t (&r)[4], uint32_t addr) {
    asm volatile("ldmatrix.sync.aligned.m8n8.x4.shared.b16 {%0,%1,%2,%3}, [%4];"
        : "=r"(r[0]), "=r"(r[1]), "=r"(r[2]), "=r"(r[3]) : "r"(addr));
}
__device__ __forceinline__ void ldsm_x2(uint32_t (&r)[2], uint32_t addr) {
    asm volatile("ldmatrix.sync.aligned.m8n8.x2.shared.b16 {%0,%1}, [%2];"
        : "=r"(r[0]), "=r"(r[1]) : "r"(addr));
}
__device__ __forceinline__ void mma16816(float (&c)[4], const uint32_t (&a)[4],
                                         uint32_t b0, uint32_t b1) {
    asm volatile("mma.sync.aligned.m16n8k16.row.col.f32.bf16.bf16.f32 "
        "{%0,%1,%2,%3}, {%4,%5,%6,%7}, {%8,%9}, {%0,%1,%2,%3};"
        : "+f"(c[0]), "+f"(c[1]), "+f"(c[2]), "+f"(c[3])
        : "r"(a[0]), "r"(a[1]), "r"(a[2]), "r"(a[3]), "r"(b0), "r"(b1));
}
__device__ __forceinline__ uint32_t bfhi2(float a, float b) {
    return (uint32_t)__bfloat16_as_ushort(__float2bfloat16_rn(a))
         | ((uint32_t)__bfloat16_as_ushort(__float2bfloat16_rn(b)) << 16);
}
__device__ __forceinline__ float bfres(float a) {
    return a - __bfloat162float(__float2bfloat16_rn(a));
}
__device__ __forceinline__ unsigned short bfbits(float a) {
    return __bfloat16_as_ushort(__float2bfloat16_rn(a));
}
__device__ __forceinline__ float fast_tanh(float x) {
    float e = __expf(2.0f * x);
    return 1.0f - 2.0f / (e + 1.0f);
}

// ---------------------------------------------------------------------------
// prep_cinit: C1 accumulator-init fragments.  grid (NBLK, 2), 512 threads.
// c[m][n] = b1[n] + sum_i xi[m][i] * W1[64+i][n]
// ---------------------------------------------------------------------------
__global__ void prep_cinit(const float* __restrict__ x,
                           const float* __restrict__ W1q, const float* __restrict__ b1q,
                           const float* __restrict__ W1p, const float* __restrict__ b1p)
{
    const int net = blockIdx.y;
    const float* W1 = net ? W1p : W1q;
    const float* b1 = net ? b1p : b1q;
    __shared__ float sW[16][128];
    __shared__ float sb[128];
    const int tid = threadIdx.x;
    for (int i = tid; i < 16 * 128; i += NTHR)
        sW[i >> 7][i & 127] = W1[(64 + (i >> 7)) * 128 + (i & 127)];
    if (tid < 128) sb[tid] = b1[tid];
    __syncthreads();

    const int wid = tid >> 5, lane = tid & 31;
    const int wm = (wid >> 2) * 32, wn = (wid & 3) * 32;
    const int mblk = blockIdx.x;
    const int m0 = mblk * TMN;

    float xi[4][16];
    #pragma unroll
    for (int h = 0; h < 4; h++) {
        const int m = m0 + wm + h * 8 + (lane >> 2);
        #pragma unroll
        for (int i = 0; i < 4; i++) {
            float4 v = __ldg((const float4*)(x + (size_t)m * 80 + 64 + 4 * i));
            xi[h][4*i] = v.x; xi[h][4*i+1] = v.y; xi[h][4*i+2] = v.z; xi[h][4*i+3] = v.w;
        }
    }
    #pragma unroll
    for (int mi = 0; mi < 2; mi++) {
        #pragma unroll
        for (int nj = 0; nj < 4; nj++) {
            #pragma unroll
            for (int e = 0; e < 4; e++) {
                const int h = mi * 2 + (e >> 1);
                const int n = wn + nj * 8 + (lane & 3) * 2 + (e & 1);
                float s = sb[n];
                #pragma unroll
                for (int i = 0; i < 16; i++) s = fmaf(xi[h][i], sW[i][n], s);
                g_C1f[net][mblk][wid][mi][nj][lane][e] = s;
            }
        }
    }
}

// ---------------------------------------------------------------------------
// prep_bfrag: build B fragments via the SAME ldmatrix addressing tc_phase
// would use, store fragment-major.  grid 2 (net), 128 threads.
// ---------------------------------------------------------------------------
__global__ void prep_bfrag(const float* __restrict__ W1q, const float* __restrict__ W2q,
                           const float* __restrict__ W1p, const float* __restrict__ W2p)
{
    const int net = blockIdx.x;
    const float* W1 = net ? W1p : W1q;
    const float* W2 = net ? W2p : W2q;
    __shared__ unsigned short img[128 * SA1];    // 34816 B
    const int tid = threadIdx.x, wid = tid >> 5, lane = tid & 31;

    // ---- B1 image: rows n 0..127, cols k 0..127 (k<64 hi, k>=64 lo), stride SA1
    for (int idx = tid; idx < 128 * 128; idx += 128) {
        const int n = idx >> 7, k = idx & 127;
        const float v = W1[(k & 63) * 128 + n];
        img[n * SA1 + k] = bfbits(k < 64 ? v : bfres(v));
    }
    __syncthreads();
    {
        const int b_nofs = (lane & 7) + ((lane >> 4) << 3);
        const int b_koff = ((lane >> 3) & 1) << 3;
        const uint32_t base = smem_u32(img) + (uint32_t)((wid * 32 + b_nofs) * SA1 + b_koff) * 2;
        for (int f = 0; f < 8; f++) {
            const int kimg = (f < 4) ? f * 16 : 64 + (f - 4) * 16;
            uint32_t r[4];
            ldsm_x4(r, base + kimg * 2);
            g_B1f[net][wid][f][0][lane] = make_uint4(r[0], r[1], r[2], r[3]);
            ldsm_x4(r, base + kimg * 2 + 16 * SA1 * 2);
            g_B1f[net][wid][f][1][lane] = make_uint4(r[0], r[1], r[2], r[3]);
        }
    }
    __syncthreads();

    // ---- B2 image: rows n 0..31, cols k 0..255 (k<128 hi, else lo), stride 264
    for (int idx = tid; idx < 32 * 256; idx += 128) {
        const int n = idx >> 8, k = idx & 255;
        const float v = W2[(k & 127) * 32 + n];
        img[n * 264 + k] = bfbits(k < 128 ? v : bfres(v));
    }
    __syncthreads();
    {
        const int l = lane & 15;
        const uint32_t base = smem_u32(img)
            + (uint32_t)((wid * 8 + (l & 7)) * 264 + (((l >> 3) & 1) << 3)) * 2;
        for (int f = 0; f < 16; f++) {
            const int kimg = (f < 8) ? f * 16 : 128 + (f - 8) * 16;
            uint32_t r[2];
            ldsm_x2(r, base + kimg * 2);
            g_B2f[net][wid][f][lane] = make_uint2(r[0], r[1]);
        }
    }
}

// ---------------------------------------------------------------------------
// One integrator phase.  512 threads, 128 nodes/block, 2 blocks/SM, 1 wave.
// ---------------------------------------------------------------------------
__global__ __launch_bounds__(NTHR, 2)
void tc_phase(float* __restrict__ state, const float* __restrict__ tfinal,
              const float* __restrict__ b2, const int* __restrict__ nbrs,
              int net, int roff, int woff, float t_base, float dt_max)
{
    extern __shared__ unsigned char smx[];
    const uint32_t sbase = smem_u32(smx);
    const int tid = threadIdx.x;
    const int wid = tid >> 5;
    const int lane = tid & 31;
    const int mblk = blockIdx.x;
    const int m0 = mblk * TMN;

    // ---- build A1 [128 x 128]: cols 0..63 = x_hi (self|nbr), 64..127 = x_lo ----
    {
        const int r = tid >> 2, part = tid & 3;   // part 0/1: self halves; 2/3: nbr halves
        const int m = m0 + r;
        float z[16];
        if (part < 2) {
            const float* p = state + (size_t)m * 80 + roff + part * 16;
            #pragma unroll
            for (int i = 0; i < 4; i++) {
                float4 v = ((const float4*)p)[i];
                z[4*i] = v.x; z[4*i+1] = v.y; z[4*i+2] = v.z; z[4*i+3] = v.w;
            }
        } else {
            const int b = m >> 12, n = m & (NN - 1);
            const int4 nb = *(const int4*)(nbrs + n * 4);
            const int nbase = b << 12;
            const int off = roff + (part - 2) * 16;
            const float* p0 = state + (size_t)(nbase + nb.x) * 80 + off;
            const float* p1 = state + (size_t)(nbase + nb.y) * 80 + off;
            const float* p2 = state + (size_t)(nbase + nb.z) * 80 + off;
            const float* p3 = state + (size_t)(nbase + nb.w) * 80 + off;
            #pragma unroll
            for (int i = 0; i < 4; i++) {
                float4 a0 = ((const float4*)p0)[i], a1 = ((const float4*)p1)[i];
                float4 a2 = ((const float4*)p2)[i], a3 = ((const float4*)p3)[i];
                z[4*i]   = 0.25f * ((a0.x + a1.x) + (a2.x + a3.x));
                z[4*i+1] = 0.25f * ((a0.y + a1.y) + (a2.y + a3.y));
                z[4*i+2] = 0.25f * ((a0.z + a1.z) + (a2.z + a3.z));
                z[4*i+3] = 0.25f * ((a0.w + a1.w) + (a2.w + a3.w));
            }
        }
        const int c0 = part * 16;
        #pragma unroll
        for (int i = 0; i < 16; i += 2) {
            *(uint32_t*)(smx + SM_A1 + (r * SA1 + c0 + i) * 2)      = bfhi2(z[i], z[i+1]);
            *(uint32_t*)(smx + SM_A1 + (r * SA1 + 64 + c0 + i) * 2) = bfhi2(bfres(z[i]), bfres(z[i+1]));
        }
    }
    __syncthreads();

    const int a_row  = lane & 15;
    const int a_koff = (lane >> 4) << 3;
    const int wm = (wid >> 2) * 32;
    const int wn = (wid & 3) * 32;

    // ---- GEMM1 accumulators seeded with b1 + xi@W1 (fragment-ordered) ----
    float acc[2][4][4];
    {
        const float4* cb = (const float4*)&g_C1f[net][mblk][wid][0][0][0][0];
        #pragma unroll
        for (int mi = 0; mi < 2; mi++)
            #pragma unroll
            for (int nj = 0; nj < 4; nj++) {
                float4 v = __ldg(cb + (mi * 4 + nj) * 32 + lane);
                acc[mi][nj][0] = v.x; acc[mi][nj][1] = v.y;
                acc[mi][nj][2] = v.z; acc[mi][nj][3] = v.w;
            }
    }

    const uint32_t aB = sbase + SM_A1 + (uint32_t)((wm + a_row) * SA1 + a_koff) * 2;

    // ---- GEMM1: x_hi@W_hi + x_hi@W_lo, then x_lo@W_hi ----
    #pragma unroll
    for (int ks = 0; ks < 4; ks++) {
        uint32_t af[2][4];
        ldsm_x4(af[0], aB + ks * 32);
        ldsm_x4(af[1], aB + ks * 32 + 16 * SA1 * 2);
        {
            const uint4 b0 = __ldg(&g_B1f[net][wn >> 5][ks][0][lane]);
            const uint4 b1v = __ldg(&g_B1f[net][wn >> 5][ks][1][lane]);
            #pragma unroll
            for (int mi = 0; mi < 2; mi++) {
                mma16816(acc[mi][0], af[mi], b0.x, b0.y);
                mma16816(acc[mi][1], af[mi], b0.z, b0.w);
                mma16816(acc[mi][2], af[mi], b1v.x, b1v.y);
                mma16816(acc[mi][3], af[mi], b1v.z, b1v.w);
            }
        }
        {
            const uint4 b0 = __ldg(&g_B1f[net][wn >> 5][4 + ks][0][lane]);
            const uint4 b1v = __ldg(&g_B1f[net][wn >> 5][4 + ks][1][lane]);
            #pragma unroll
            for (int mi = 0; mi < 2; mi++) {
                mma16816(acc[mi][0], af[mi], b0.x, b0.y);
                mma16816(acc[mi][1], af[mi], b0.z, b0.w);
                mma16816(acc[mi][2], af[mi], b1v.x, b1v.y);
                mma16816(acc[mi][3], af[mi], b1v.z, b1v.w);
            }
        }
    }
    #pragma unroll
    for (int ks = 0; ks < 4; ks++) {
        uint32_t af[2][4];
        ldsm_x4(af[0], aB + (64 + ks * 16) * 2);
        ldsm_x4(af[1], aB + (64 + ks * 16) * 2 + 16 * SA1 * 2);
        const uint4 b0 = __ldg(&g_B1f[net][wn >> 5][ks][0][lane]);
        const uint4 b1v = __ldg(&g_B1f[net][wn >> 5][ks][1][lane]);
        #pragma unroll
        for (int mi = 0; mi < 2; mi++) {
            mma16816(acc[mi][0], af[mi], b0.x, b0.y);
            mma16816(acc[mi][1], af[mi], b0.z, b0.w);
            mma16816(acc[mi][2], af[mi], b1v.x, b1v.y);
            mma16816(acc[mi][3], af[mi], b1v.z, b1v.w);
        }
    }

    // ---- tanh -> h (disjoint smem region; no barrier needed before writes) ----
    {
        const int rb = wm + (lane >> 2);
        const int cbs = wn + (lane & 3) * 2;
        #pragma unroll
        for (int mi = 0; mi < 2; mi++) {
            #pragma unroll
            for (int nj = 0; nj < 4; nj++) {
                const int c = cbs + nj * 8;
                #pragma unroll
                for (int hh = 0; hh < 2; hh++) {
                    const int r = rb + mi * 16 + hh * 8;
                    const float t0 = fast_tanh(acc[mi][nj][hh * 2 + 0]);
                    const float t1 = fast_tanh(acc[mi][nj][hh * 2 + 1]);
                    *(uint32_t*)(smx + SM_H + (r * SH + c) * 2)       = bfhi2(t0, t1);
                    *(uint32_t*)(smx + SM_H + (r * SH + 136 + c) * 2) = bfhi2(bfres(t0), bfres(t1));
                }
            }
        }
    }
    __syncthreads();

    // ---- GEMM2: h_hi@W2_hi + h_hi@W2_lo + h_lo@W2_hi ----
    const int wn2 = (wid & 3) * 8;
    float acc2[2][4];
    #pragma unroll
    for (int mi = 0; mi < 2; mi++)
        #pragma unroll
        for (int e = 0; e < 4; e++) acc2[mi][e] = 0.0f;

    const uint32_t hB = sbase + SM_H + (uint32_t)((wm + a_row) * SH + a_koff) * 2;
    #pragma unroll
    for (int ks = 0; ks < 8; ks++) {
        uint32_t af[2][4];
        ldsm_x4(af[0], hB + ks * 32);
        ldsm_x4(af[1], hB + ks * 32 + 16 * SH * 2);
        const uint2 bh = __ldg(&g_B2f[net][wn2 >> 3][ks][lane]);
        const uint2 bl = __ldg(&g_B2f[net][wn2 >> 3][8 + ks][lane]);
        mma16816(acc2[0], af[0], bh.x, bh.y);
        mma16816(acc2[1], af[1], bh.x, bh.y);
        mma16816(acc2[0], af[0], bl.x, bl.y);
        mma16816(acc2[1], af[1], bl.x, bl.y);
    }
    #pragma unroll
    for (int ks = 0; ks < 8; ks++) {
        uint32_t af[2][4];
        ldsm_x4(af[0], hB + (136 + ks * 16) * 2);
        ldsm_x4(af[1], hB + (136 + ks * 16) * 2 + 16 * SH * 2);
        const uint2 bh = __ldg(&g_B2f[net][wn2 >> 3][ks][lane]);
        mma16816(acc2[0], af[0], bh.x, bh.y);
        mma16816(acc2[1], af[1], bh.x, bh.y);
    }

    // ---- epilogue: state += dt * (C2 + b2) ----
    {
        const float tf = __ldg(tfinal + (m0 >> 12));
        const float dt = fminf(fmaxf(tf - t_base, 0.0f), dt_max);
        const int c0 = wn2 + (lane & 3) * 2;
        const float b2v0 = __ldg(b2 + c0);
        const float b2v1 = __ldg(b2 + c0 + 1);
        #pragma unroll
        for (int mi = 0; mi < 2; mi++) {
            const int r0 = m0 + wm + mi * 16 + (lane >> 2);
            float* p0 = state + (size_t)r0 * 80 + woff + c0;
            p0[0] = fmaf(dt, acc2[mi][0] + b2v0, p0[0]);
            p0[1] = fmaf(dt, acc2[mi][1] + b2v1, p0[1]);
            float* p1 = state + (size_t)(r0 + 8) * 80 + woff + c0;
            p1[0] = fmaf(dt, acc2[mi][2] + b2v0, p1[0]);
            p1[1] = fmaf(dt, acc2[mi][3] + b2v1, p1[1]);
        }
    }
}

// ---------------------------------------------------------------------------
extern "C" void kernel_launch(void* const* d_in, const int* in_sizes, int n_in,
                              void* d_out, int out_size)
{
    const float* x   = (const float*)d_in[0];
    const float* tfi = (const float*)d_in[1];
    const float* W1q = (const float*)d_in[2];
    const float* b1q = (const float*)d_in[3];
    const float* W2q = (const float*)d_in[4];
    const float* b2q = (const float*)d_in[5];
    const float* W1p = (const float*)d_in[6];
    const float* b1p = (const float*)d_in[7];
    const float* W2p = (const float*)d_in[8];
    const float* b2p = (const float*)d_in[9];
    const int*  nbrs = (const int*)d_in[10];
    float* out = (float*)d_out;

    cudaFuncSetAttribute(tc_phase, cudaFuncAttributeMaxDynamicSharedMemorySize, SM_TOTAL);

    cudaMemcpyAsync(out, x, (size_t)NODES * 80 * sizeof(float),
                    cudaMemcpyDeviceToDevice);
    prep_cinit<<<dim3(NBLK, 2), NTHR>>>(x, W1q, b1q, W1p, b1p);
    prep_bfrag<<<2, 128>>>(W1q, W2q, W1p, W2p);

    float tq = 0.0f, tp = 0.0f;
    for (int k = 0; k < N_STEPS; k++) {
        const float rho = (k == 0) ? 0.5f : 1.0f;
        // q-update: reads p (offset 32), writes q (offset 0)
        tc_phase<<<NBLK, NTHR, SM_TOTAL>>>(out, tfi, b2q, nbrs, 0, POFF, 0, tq, rho * DT_STEP);
        tq += rho * DT_STEP;
        // p-update: reads q (offset 0), writes p (offset 32)
        tc_phase<<<NBLK, NTHR, SM_TOTAL>>>(out, tfi, b2p, nbrs, 1, 0, POFF, tp, DT_STEP);
        tp += DT_STEP;
    }
}

// round 9
// speedup vs baseline: 3.7575x; 1.0263x over previous
#include <cuda_runtime.h>
#include <cuda_bf16.h>
#include <cstdint>

#define NN       4096
#define NODES    32768
#define DT_STEP  0.25f
#define N_STEPS  18
#define TMN      128                 // nodes (M) per block
#define NBLK     (NODES / TMN)       // 256
#define NTHR     512
#define POFF     32                  // p-field offset within 80-float node record

#define SA1      136                 // A1 row stride (elems): 128 K + 8 pad
#define SH       272                 // h row stride (elems): hi at col 0, lo at col 136
#define SM_A1    0
#define SM_H     (128 * SA1 * 2)                  // 34816
#define SM_TOTAL (SM_H + 128 * SH * 2)            // 104448 bytes

// B1 fragments: [net][wn/32][f(0..3 hi,4..7 lo)][half][lane] (ldmatrix x4 regs)
__device__ uint4 g_B1f[2][4][8][2][32];
// B2 fragments: [net][wn2/8][f(0..7 hi,8..15 lo)][lane] (ldmatrix x2 regs)
__device__ uint2 g_B2f[2][4][16][32];
// xi A-side fragments: [mblk][wm/32][hi/lo][mi][lane] (built once; xi is step-invariant)
__device__ uint4 g_XIf[NBLK][4][2][2][32];                 // 2 MB
// xi/bias B-side fragments: [net][wn/32][f: 0=WXhi 1=WXlo 2=bias][half][lane]
__device__ uint4 g_BXf[2][4][3][2][32];

// ---------------------------------------------------------------------------
__device__ __forceinline__ uint32_t smem_u32(const void* p) {
    uint32_t a;
    asm("{ .reg .u64 t; cvta.to.shared.u64 t, %1; cvt.u32.u64 %0, t; }" : "=r"(a) : "l"(p));
    return a;
}
__device__ __forceinline__ void ldsm_x4(uint32_t (&r)[4], uint32_t addr) {
    asm volatile("ldmatrix.sync.aligned.m8n8.x4.shared.b16 {%0,%1,%2,%3}, [%4];"
        : "=r"(r[0]), "=r"(r[1]), "=r"(r[2]), "=r"(r[3]) : "r"(addr));
}
__device__ __forceinline__ void ldsm_x2(uint32_t (&r)[2], uint32_t addr) {
    asm volatile("ldmatrix.sync.aligned.m8n8.x2.shared.b16 {%0,%1}, [%2];"
        : "=r"(r[0]), "=r"(r[1]) : "r"(addr));
}
__device__ __forceinline__ void mma16816(float (&c)[4], const uint32_t (&a)[4],
                                         uint32_t b0, uint32_t b1) {
    asm volatile("mma.sync.aligned.m16n8k16.row.col.f32.bf16.bf16.f32 "
        "{%0,%1,%2,%3}, {%4,%5,%6,%7}, {%8,%9}, {%0,%1,%2,%3};"
        : "+f"(c[0]), "+f"(c[1]), "+f"(c[2]), "+f"(c[3])
        : "r"(a[0]), "r"(a[1]), "r"(a[2]), "r"(a[3]), "r"(b0), "r"(b1));
}
__device__ __forceinline__ uint32_t bfhi2(float a, float b) {
    return (uint32_t)__bfloat16_as_ushort(__float2bfloat16_rn(a))
         | ((uint32_t)__bfloat16_as_ushort(__float2bfloat16_rn(b)) << 16);
}
__device__ __forceinline__ float bfres(float a) {
    return a - __bfloat162float(__float2bfloat16_rn(a));
}
__device__ __forceinline__ unsigned short bfbits(float a) {
    return __bfloat16_as_ushort(__float2bfloat16_rn(a));
}
__device__ __forceinline__ float fast_tanh(float x) {
    float e = __expf(2.0f * x);
    return 1.0f - 2.0f / (e + 1.0f);
}

// ---------------------------------------------------------------------------
// prep_xifrag: per-node xi bf16 hi/lo A-fragments via ldmatrix.
// grid NBLK, 128 threads (4 warps, one per wm tile).
// ---------------------------------------------------------------------------
__global__ void prep_xifrag(const float* __restrict__ x)
{
    __shared__ unsigned short img[128 * 40];     // rows: node, cols 0..15 hi, 16..31 lo
    const int tid = threadIdx.x, wid = tid >> 5, lane = tid & 31;
    const int mblk = blockIdx.x;
    const int m = mblk * TMN + tid;
    float xi[16];
    #pragma unroll
    for (int i = 0; i < 4; i++) {
        float4 v = __ldg((const float4*)(x + (size_t)m * 80 + 64 + 4 * i));
        xi[4*i] = v.x; xi[4*i+1] = v.y; xi[4*i+2] = v.z; xi[4*i+3] = v.w;
    }
    #pragma unroll
    for (int i = 0; i < 16; i++) {
        img[tid * 40 + i]      = bfbits(xi[i]);
        img[tid * 40 + 16 + i] = bfbits(bfres(xi[i]));
    }
    __syncthreads();

    const int a_row  = lane & 15;
    const int a_koff = (lane >> 4) << 3;
    #pragma unroll
    for (int hl = 0; hl < 2; hl++)
        #pragma unroll
        for (int mi = 0; mi < 2; mi++) {
            const uint32_t addr = smem_u32(img)
                + (uint32_t)((wid * 32 + mi * 16 + a_row) * 40 + hl * 16 + a_koff) * 2;
            uint32_t r[4];
            ldsm_x4(r, addr);
            g_XIf[mblk][wid][hl][mi][lane] = make_uint4(r[0], r[1], r[2], r[3]);
        }
}

// ---------------------------------------------------------------------------
// prep_bfrag: B fragments via the SAME ldmatrix addressing tc_phase uses.
// grid 2 (net), 128 threads.
// ---------------------------------------------------------------------------
__global__ void prep_bfrag(const float* __restrict__ W1q, const float* __restrict__ b1q,
                           const float* __restrict__ W2q,
                           const float* __restrict__ W1p, const float* __restrict__ b1p,
                           const float* __restrict__ W2p)
{
    const int net = blockIdx.x;
    const float* W1 = net ? W1p : W1q;
    const float* b1 = net ? b1p : b1q;
    const float* W2 = net ? W2p : W2q;
    __shared__ unsigned short img[128 * SA1];    // 34816 B, reused 3x
    const int tid = threadIdx.x, wid = tid >> 5, lane = tid & 31;
    const int b_nofs = (lane & 7) + ((lane >> 4) << 3);
    const int b_koff = ((lane >> 3) & 1) << 3;

    // ---- B1 image: rows n 0..127, cols k 0..127 (k<64 hi, k>=64 lo), stride SA1
    for (int idx = tid; idx < 128 * 128; idx += 128) {
        const int n = idx >> 7, k = idx & 127;
        const float v = W1[(k & 63) * 128 + n];
        img[n * SA1 + k] = bfbits(k < 64 ? v : bfres(v));
    }
    __syncthreads();
    {
        const uint32_t base = smem_u32(img) + (uint32_t)((wid * 32 + b_nofs) * SA1 + b_koff) * 2;
        for (int f = 0; f < 8; f++) {
            const int kimg = (f < 4) ? f * 16 : 64 + (f - 4) * 16;
            uint32_t r[4];
            ldsm_x4(r, base + kimg * 2);
            g_B1f[net][wid][f][0][lane] = make_uint4(r[0], r[1], r[2], r[3]);
            ldsm_x4(r, base + kimg * 2 + 16 * SA1 * 2);
            g_B1f[net][wid][f][1][lane] = make_uint4(r[0], r[1], r[2], r[3]);
        }
    }
    __syncthreads();

    // ---- B2 image: rows n 0..31, cols k 0..255 (k<128 hi, else lo), stride 264
    for (int idx = tid; idx < 32 * 256; idx += 128) {
        const int n = idx >> 8, k = idx & 255;
        const float v = W2[(k & 127) * 32 + n];
        img[n * 264 + k] = bfbits(k < 128 ? v : bfres(v));
    }
    __syncthreads();
    {
        const int l = lane & 15;
        const uint32_t base = smem_u32(img)
            + (uint32_t)((wid * 8 + (l & 7)) * 264 + (((l >> 3) & 1) << 3)) * 2;
        for (int f = 0; f < 16; f++) {
            const int kimg = (f < 8) ? f * 16 : 128 + (f - 8) * 16;
            uint32_t r[2];
            ldsm_x2(r, base + kimg * 2);
            g_B2f[net][wid][f][lane] = make_uint2(r[0], r[1]);
        }
    }
    __syncthreads();

    // ---- X image: rows n 0..127, cols 0..15 WXhi, 16..31 WXlo, 32=b1_hi 33=b1_lo,
    //      34..47 zero.  stride 56.
    for (int idx = tid; idx < 128 * 48; idx += 128) {
        const int n = idx / 48, k = idx % 48;
        float v = 0.0f;
        if (k < 16)       v = W1[(64 + k) * 128 + n];
        else if (k < 32)  v = bfres(W1[(64 + k - 16) * 128 + n]);
        else if (k == 32) v = b1[n];
        else if (k == 33) v = bfres(b1[n]);
        img[n * 56 + k] = bfbits(v);
    }
    __syncthreads();
    {
        const uint32_t base = smem_u32(img) + (uint32_t)((wid * 32 + b_nofs) * 56 + b_koff) * 2;
        for (int f = 0; f < 3; f++) {
            uint32_t r[4];
            ldsm_x4(r, base + f * 16 * 2);
            g_BXf[net][wid][f][0][lane] = make_uint4(r[0], r[1], r[2], r[3]);
            ldsm_x4(r, base + f * 16 * 2 + 16 * 56 * 2);
            g_BXf[net][wid][f][1][lane] = make_uint4(r[0], r[1], r[2], r[3]);
        }
    }
}

// ---------------------------------------------------------------------------
// One integrator phase.  512 threads, 128 nodes/block, 2 blocks/SM, 1 wave.
// ---------------------------------------------------------------------------
__global__ __launch_bounds__(NTHR, 2)
void tc_phase(float* __restrict__ state, const float* __restrict__ tfinal,
              const float* __restrict__ b2, const int* __restrict__ nbrs,
              int net, int roff, int woff, float t_base, float dt_max)
{
    extern __shared__ unsigned char smx[];
    const uint32_t sbase = smem_u32(smx);
    const int tid = threadIdx.x;
    const int wid = tid >> 5;
    const int lane = tid & 31;
    const int mblk = blockIdx.x;
    const int m0 = mblk * TMN;

    // ---- build A1 [128 x 128]: cols 0..63 = x_hi (self|nbr), 64..127 = x_lo ----
    {
        const int r = tid >> 2, part = tid & 3;   // part 0/1: self halves; 2/3: nbr halves
        const int m = m0 + r;
        float z[16];
        if (part < 2) {
            const float* p = state + (size_t)m * 80 + roff + part * 16;
            #pragma unroll
            for (int i = 0; i < 4; i++) {
                float4 v = ((const float4*)p)[i];
                z[4*i] = v.x; z[4*i+1] = v.y; z[4*i+2] = v.z; z[4*i+3] = v.w;
            }
        } else {
            const int b = m >> 12, n = m & (NN - 1);
            const int4 nb = *(const int4*)(nbrs + n * 4);
            const int nbase = b << 12;
            const int off = roff + (part - 2) * 16;
            const float* p0 = state + (size_t)(nbase + nb.x) * 80 + off;
            const float* p1 = state + (size_t)(nbase + nb.y) * 80 + off;
            const float* p2 = state + (size_t)(nbase + nb.z) * 80 + off;
            const float* p3 = state + (size_t)(nbase + nb.w) * 80 + off;
            #pragma unroll
            for (int i = 0; i < 4; i++) {
                float4 a0 = ((const float4*)p0)[i], a1 = ((const float4*)p1)[i];
                float4 a2 = ((const float4*)p2)[i], a3 = ((const float4*)p3)[i];
                z[4*i]   = 0.25f * ((a0.x + a1.x) + (a2.x + a3.x));
                z[4*i+1] = 0.25f * ((a0.y + a1.y) + (a2.y + a3.y));
                z[4*i+2] = 0.25f * ((a0.z + a1.z) + (a2.z + a3.z));
                z[4*i+3] = 0.25f * ((a0.w + a1.w) + (a2.w + a3.w));
            }
        }
        const int c0 = part * 16;
        #pragma unroll
        for (int i = 0; i < 16; i += 2) {
            *(uint32_t*)(smx + SM_A1 + (r * SA1 + c0 + i) * 2)      = bfhi2(z[i], z[i+1]);
            *(uint32_t*)(smx + SM_A1 + (r * SA1 + 64 + c0 + i) * 2) = bfhi2(bfres(z[i]), bfres(z[i+1]));
        }
    }

    const int a_row  = lane & 15;
    const int a_koff = (lane >> 4) << 3;
    const int wm = (wid >> 2) * 32;
    const int wn = (wid & 3) * 32;
    const int wmI = wid >> 2, wnI = wid & 3;

    // ---- xi + bias k-steps (global fragments only -> run BEFORE the barrier,
    //      overlapping other warps' A1 stores) ----
    float acc[2][4][4];
    #pragma unroll
    for (int mi = 0; mi < 2; mi++)
        #pragma unroll
        for (int nj = 0; nj < 4; nj++)
            #pragma unroll
            for (int e = 0; e < 4; e++) acc[mi][nj][e] = 0.0f;

    {
        uint32_t aH[2][4], aL[2][4];
        #pragma unroll
        for (int mi = 0; mi < 2; mi++) {
            const uint4 vh = __ldg(&g_XIf[mblk][wmI][0][mi][lane]);
            aH[mi][0] = vh.x; aH[mi][1] = vh.y; aH[mi][2] = vh.z; aH[mi][3] = vh.w;
            const uint4 vl = __ldg(&g_XIf[mblk][wmI][1][mi][lane]);
            aL[mi][0] = vl.x; aL[mi][1] = vl.y; aL[mi][2] = vl.z; aL[mi][3] = vl.w;
        }
        {   // X0: xiH @ WXhi ; X1: xiL @ WXhi
            const uint4 b0 = __ldg(&g_BXf[net][wnI][0][0][lane]);
            const uint4 b1v = __ldg(&g_BXf[net][wnI][0][1][lane]);
            #pragma unroll
            for (int mi = 0; mi < 2; mi++) {
                mma16816(acc[mi][0], aH[mi], b0.x, b0.y);
                mma16816(acc[mi][1], aH[mi], b0.z, b0.w);
                mma16816(acc[mi][2], aH[mi], b1v.x, b1v.y);
                mma16816(acc[mi][3], aH[mi], b1v.z, b1v.w);
                mma16816(acc[mi][0], aL[mi], b0.x, b0.y);
                mma16816(acc[mi][1], aL[mi], b0.z, b0.w);
                mma16816(acc[mi][2], aL[mi], b1v.x, b1v.y);
                mma16816(acc[mi][3], aL[mi], b1v.z, b1v.w);
            }
        }
        {   // X2: xiH @ WXlo
            const uint4 b0 = __ldg(&g_BXf[net][wnI][1][0][lane]);
            const uint4 b1v = __ldg(&g_BXf[net][wnI][1][1][lane]);
            #pragma unroll
            for (int mi = 0; mi < 2; mi++) {
                mma16816(acc[mi][0], aH[mi], b0.x, b0.y);
                mma16816(acc[mi][1], aH[mi], b0.z, b0.w);
                mma16816(acc[mi][2], aH[mi], b1v.x, b1v.y);
                mma16816(acc[mi][3], aH[mi], b1v.z, b1v.w);
            }
        }
        {   // X3: bias.  A: cols 0,1 = 1.0, rest 0 (inline, no load)
            uint32_t aBias[4];
            const uint32_t one2 = ((lane & 3) == 0) ? 0x3F803F80u : 0u;
            aBias[0] = one2; aBias[1] = one2; aBias[2] = 0u; aBias[3] = 0u;
            const uint4 b0 = __ldg(&g_BXf[net][wnI][2][0][lane]);
            const uint4 b1v = __ldg(&g_BXf[net][wnI][2][1][lane]);
            #pragma unroll
            for (int mi = 0; mi < 2; mi++) {
                mma16816(acc[mi][0], aBias, b0.x, b0.y);
                mma16816(acc[mi][1], aBias, b0.z, b0.w);
                mma16816(acc[mi][2], aBias, b1v.x, b1v.y);
                mma16816(acc[mi][3], aBias, b1v.z, b1v.w);
            }
        }
    }
    __syncthreads();

    const uint32_t aB = sbase + SM_A1 + (uint32_t)((wm + a_row) * SA1 + a_koff) * 2;

    // ---- GEMM1: x_hi@W_hi + x_hi@W_lo, then x_lo@W_hi ----
    #pragma unroll
    for (int ks = 0; ks < 4; ks++) {
        uint32_t af[2][4];
        ldsm_x4(af[0], aB + ks * 32);
        ldsm_x4(af[1], aB + ks * 32 + 16 * SA1 * 2);
        {
            const uint4 b0 = __ldg(&g_B1f[net][wnI][ks][0][lane]);
            const uint4 b1v = __ldg(&g_B1f[net][wnI][ks][1][lane]);
            #pragma unroll
            for (int mi = 0; mi < 2; mi++) {
                mma16816(acc[mi][0], af[mi], b0.x, b0.y);
                mma16816(acc[mi][1], af[mi], b0.z, b0.w);
                mma16816(acc[mi][2], af[mi], b1v.x, b1v.y);
                mma16816(acc[mi][3], af[mi], b1v.z, b1v.w);
            }
        }
        {
            const uint4 b0 = __ldg(&g_B1f[net][wnI][4 + ks][0][lane]);
            const uint4 b1v = __ldg(&g_B1f[net][wnI][4 + ks][1][lane]);
            #pragma unroll
            for (int mi = 0; mi < 2; mi++) {
                mma16816(acc[mi][0], af[mi], b0.x, b0.y);
                mma16816(acc[mi][1], af[mi], b0.z, b0.w);
                mma16816(acc[mi][2], af[mi], b1v.x, b1v.y);
                mma16816(acc[mi][3], af[mi], b1v.z, b1v.w);
            }
        }
    }
    #pragma unroll
    for (int ks = 0; ks < 4; ks++) {
        uint32_t af[2][4];
        ldsm_x4(af[0], aB + (64 + ks * 16) * 2);
        ldsm_x4(af[1], aB + (64 + ks * 16) * 2 + 16 * SA1 * 2);
        const uint4 b0 = __ldg(&g_B1f[net][wnI][ks][0][lane]);
        const uint4 b1v = __ldg(&g_B1f[net][wnI][ks][1][lane]);
        #pragma unroll
        for (int mi = 0; mi < 2; mi++) {
            mma16816(acc[mi][0], af[mi], b0.x, b0.y);
            mma16816(acc[mi][1], af[mi], b0.z, b0.w);
            mma16816(acc[mi][2], af[mi], b1v.x, b1v.y);
            mma16816(acc[mi][3], af[mi], b1v.z, b1v.w);
        }
    }

    // ---- tanh -> h (disjoint smem region) ----
    {
        const int rb = wm + (lane >> 2);
        const int cbs = wn + (lane & 3) * 2;
        #pragma unroll
        for (int mi = 0; mi < 2; mi++) {
            #pragma unroll
            for (int nj = 0; nj < 4; nj++) {
                const int c = cbs + nj * 8;
                #pragma unroll
                for (int hh = 0; hh < 2; hh++) {
                    const int r = rb + mi * 16 + hh * 8;
                    const float t0 = fast_tanh(acc[mi][nj][hh * 2 + 0]);
                    const float t1 = fast_tanh(acc[mi][nj][hh * 2 + 1]);
                    *(uint32_t*)(smx + SM_H + (r * SH + c) * 2)       = bfhi2(t0, t1);
                    *(uint32_t*)(smx + SM_H + (r * SH + 136 + c) * 2) = bfhi2(bfres(t0), bfres(t1));
                }
            }
        }
    }
    __syncthreads();

    // ---- GEMM2: h_hi@W2_hi + h_hi@W2_lo + h_lo@W2_hi ----
    const int wn2 = (wid & 3) * 8;
    float acc2[2][4];
    #pragma unroll
    for (int mi = 0; mi < 2; mi++)
        #pragma unroll
        for (int e = 0; e < 4; e++) acc2[mi][e] = 0.0f;

    const uint32_t hB = sbase + SM_H + (uint32_t)((wm + a_row) * SH + a_koff) * 2;
    #pragma unroll
    for (int ks = 0; ks < 8; ks++) {
        uint32_t af[2][4];
        ldsm_x4(af[0], hB + ks * 32);
        ldsm_x4(af[1], hB + ks * 32 + 16 * SH * 2);
        const uint2 bh = __ldg(&g_B2f[net][wn2 >> 3][ks][lane]);
        const uint2 bl = __ldg(&g_B2f[net][wn2 >> 3][8 + ks][lane]);
        mma16816(acc2[0], af[0], bh.x, bh.y);
        mma16816(acc2[1], af[1], bh.x, bh.y);
        mma16816(acc2[0], af[0], bl.x, bl.y);
        mma16816(acc2[1], af[1], bl.x, bl.y);
    }
    #pragma unroll
    for (int ks = 0; ks < 8; ks++) {
        uint32_t af[2][4];
        ldsm_x4(af[0], hB + (136 + ks * 16) * 2);
        ldsm_x4(af[1], hB + (136 + ks * 16) * 2 + 16 * SH * 2);
        const uint2 bh = __ldg(&g_B2f[net][wn2 >> 3][ks][lane]);
        mma16816(acc2[0], af[0], bh.x, bh.y);
        mma16816(acc2[1], af[1], bh.x, bh.y);
    }

    // ---- epilogue: state += dt * (C2 + b2) ----
    {
        const float tf = __ldg(tfinal + (m0 >> 12));
        const float dt = fminf(fmaxf(tf - t_base, 0.0f), dt_max);
        const int c0 = wn2 + (lane & 3) * 2;
        const float b2v0 = __ldg(b2 + c0);
        const float b2v1 = __ldg(b2 + c0 + 1);
        #pragma unroll
        for (int mi = 0; mi < 2; mi++) {
            const int r0 = m0 + wm + mi * 16 + (lane >> 2);
            float* p0 = state + (size_t)r0 * 80 + woff + c0;
            p0[0] = fmaf(dt, acc2[mi][0] + b2v0, p0[0]);
            p0[1] = fmaf(dt, acc2[mi][1] + b2v1, p0[1]);
            float* p1 = state + (size_t)(r0 + 8) * 80 + woff + c0;
            p1[0] = fmaf(dt, acc2[mi][2] + b2v0, p1[0]);
            p1[1] = fmaf(dt, acc2[mi][3] + b2v1, p1[1]);
        }
    }
}

// ---------------------------------------------------------------------------
extern "C" void kernel_launch(void* const* d_in, const int* in_sizes, int n_in,
                              void* d_out, int out_size)
{
    const float* x   = (const float*)d_in[0];
    const float* tfi = (const float*)d_in[1];
    const float* W1q = (const float*)d_in[2];
    const float* b1q = (const float*)d_in[3];
    const float* W2q = (const float*)d_in[4];
    const float* b2q = (const float*)d_in[5];
    const float* W1p = (const float*)d_in[6];
    const float* b1p = (const float*)d_in[7];
    const float* W2p = (const float*)d_in[8];
    const float* b2p = (const float*)d_in[9];
    const int*  nbrs = (const int*)d_in[10];
    float* out = (float*)d_out;

    cudaFuncSetAttribute(tc_phase, cudaFuncAttributeMaxDynamicSharedMemorySize, SM_TOTAL);

    cudaMemcpyAsync(out, x, (size_t)NODES * 80 * sizeof(float),
                    cudaMemcpyDeviceToDevice);
    prep_xifrag<<<NBLK, 128>>>(x);
    prep_bfrag<<<2, 128>>>(W1q, b1q, W2q, W1p, b1p, W2p);

    float tq = 0.0f, tp = 0.0f;
    for (int k = 0; k < N_STEPS; k++) {
        const float rho = (k == 0) ? 0.5f : 1.0f;
        // q-update: reads p (offset 32), writes q (offset 0)
        tc_phase<<<NBLK, NTHR, SM_TOTAL>>>(out, tfi, b2q, nbrs, 0, POFF, 0, tq, rho * DT_STEP);
        tq += rho * DT_STEP;
        // p-update: reads q (offset 0), writes p (offset 32)
        tc_phase<<<NBLK, NTHR, SM_TOTAL>>>(out, tfi, b2p, nbrs, 1, 0, POFF, tp, DT_STEP);
        tp += DT_STEP;
    }
}

// round 11
// speedup vs baseline: 4.2160x; 1.1220x over previous
#include <cuda_runtime.h>
#include <cuda_bf16.h>
#include <cstdint>

#define NN       4096
#define NODES    32768
#define DT_STEP  0.25f
#define N_STEPS  18
#define TMN      64                  // nodes (M) per block
#define NBLK     (NODES / TMN)       // 512
#define NTHR     256
#define POFF     32                  // p-field offset within 80-float node record

#define SA       136                 // row stride (elems) = 272 B  (16 mod 128 -> conflict-free ldsm)
#define SM_A1    0                                 // A1: 64 x 136 x 2B = 17408
#define SM_HH    17408                             // h_hi: 64 x 136 x 2B
#define SM_HL    (17408 * 2)                       // h_lo: 64 x 136 x 2B
#define SM_TOTAL (17408 * 3)                       // 52224 B -> 4 blocks/SM

// B1 fragments: [net][wn/32][f(0..3 hi,4..7 lo)][half][lane] (ldmatrix x4 regs)
__device__ uint4 g_B1f[2][4][8][2][32];
// B2 fragments: [net][wn2/8][f(0..7 hi,8..15 lo)][lane] (ldmatrix x2 regs)
__device__ uint2 g_B2f[2][4][16][32];
// xi A-side fragments per 32-node group: [g][hi/lo][mi][lane]
__device__ uint4 g_XIf[NODES / 32][2][2][32];
// xi/bias B-side fragments: [net][wn/32][f: 0=WXhi 1=WXlo 2=bias][half][lane]
__device__ uint4 g_BXf[2][4][3][2][32];

// ---------------------------------------------------------------------------
__device__ __forceinline__ uint32_t smem_u32(const void* p) {
    uint32_t a;
    asm("{ .reg .u64 t; cvta.to.shared.u64 t, %1; cvt.u32.u64 %0, t; }" : "=r"(a) : "l"(p));
    return a;
}
__device__ __forceinline__ void ldsm_x4(uint32_t (&r)[4], uint32_t addr) {
    asm volatile("ldmatrix.sync.aligned.m8n8.x4.shared.b16 {%0,%1,%2,%3}, [%4];"
        : "=r"(r[0]), "=r"(r[1]), "=r"(r[2]), "=r"(r[3]) : "r"(addr));
}
__device__ __forceinline__ void ldsm_x2(uint32_t (&r)[2], uint32_t addr) {
    asm volatile("ldmatrix.sync.aligned.m8n8.x2.shared.b16 {%0,%1}, [%2];"
        : "=r"(r[0]), "=r"(r[1]) : "r"(addr));
}
__device__ __forceinline__ void mma16816(float (&c)[4], const uint32_t (&a)[4],
                                         uint32_t b0, uint32_t b1) {
    asm volatile("mma.sync.aligned.m16n8k16.row.col.f32.bf16.bf16.f32 "
        "{%0,%1,%2,%3}, {%4,%5,%6,%7}, {%8,%9}, {%0,%1,%2,%3};"
        : "+f"(c[0]), "+f"(c[1]), "+f"(c[2]), "+f"(c[3])
        : "r"(a[0]), "r"(a[1]), "r"(a[2]), "r"(a[3]), "r"(b0), "r"(b1));
}
__device__ __forceinline__ uint32_t bfhi2(float a, float b) {
    return (uint32_t)__bfloat16_as_ushort(__float2bfloat16_rn(a))
         | ((uint32_t)__bfloat16_as_ushort(__float2bfloat16_rn(b)) << 16);
}
__device__ __forceinline__ float bfres(float a) {
    return a - __bfloat162float(__float2bfloat16_rn(a));
}
__device__ __forceinline__ unsigned short bfbits(float a) {
    return __bfloat16_as_ushort(__float2bfloat16_rn(a));
}
__device__ __forceinline__ float fast_tanh(float x) {
    float e = __expf(2.0f * x);
    return 1.0f - 2.0f / (e + 1.0f);
}

// ---------------------------------------------------------------------------
// prep_xifrag: per-node xi bf16 hi/lo A-fragments via ldmatrix.
// grid 256, 128 threads (4 warps, one 32-row group per warp).
// ---------------------------------------------------------------------------
__global__ void prep_xifrag(const float* __restrict__ x)
{
    __shared__ unsigned short img[128 * 40];     // rows: node, cols 0..15 hi, 16..31 lo
    const int tid = threadIdx.x, wid = tid >> 5, lane = tid & 31;
    const int m = blockIdx.x * 128 + tid;
    float xi[16];
    #pragma unroll
    for (int i = 0; i < 4; i++) {
        float4 v = __ldg((const float4*)(x + (size_t)m * 80 + 64 + 4 * i));
        xi[4*i] = v.x; xi[4*i+1] = v.y; xi[4*i+2] = v.z; xi[4*i+3] = v.w;
    }
    #pragma unroll
    for (int i = 0; i < 16; i++) {
        img[tid * 40 + i]      = bfbits(xi[i]);
        img[tid * 40 + 16 + i] = bfbits(bfres(xi[i]));
    }
    __syncthreads();

    const int a_row  = lane & 15;
    const int a_koff = (lane >> 4) << 3;
    const int g = blockIdx.x * 4 + wid;
    #pragma unroll
    for (int hl = 0; hl < 2; hl++)
        #pragma unroll
        for (int mi = 0; mi < 2; mi++) {
            const uint32_t addr = smem_u32(img)
                + (uint32_t)((wid * 32 + mi * 16 + a_row) * 40 + hl * 16 + a_koff) * 2;
            uint32_t r[4];
            ldsm_x4(r, addr);
            g_XIf[g][hl][mi][lane] = make_uint4(r[0], r[1], r[2], r[3]);
        }
}

// ---------------------------------------------------------------------------
// prep_bfrag: B fragments via the SAME ldmatrix addressing tc_phase uses.
// grid 2 (net), 128 threads.
// ---------------------------------------------------------------------------
__global__ void prep_bfrag(const float* __restrict__ W1q, const float* __restrict__ b1q,
                           const float* __restrict__ W2q,
                           const float* __restrict__ W1p, const float* __restrict__ b1p,
                           const float* __restrict__ W2p)
{
    const int net = blockIdx.x;
    const float* W1 = net ? W1p : W1q;
    const float* b1 = net ? b1p : b1q;
    const float* W2 = net ? W2p : W2q;
    __shared__ unsigned short img[128 * SA];     // reused 3x
    const int tid = threadIdx.x, wid = tid >> 5, lane = tid & 31;
    const int b_nofs = (lane & 7) + ((lane >> 4) << 3);
    const int b_koff = ((lane >> 3) & 1) << 3;

    // ---- B1 image: rows n 0..127, cols k 0..127 (k<64 hi, k>=64 lo), stride SA
    for (int idx = tid; idx < 128 * 128; idx += 128) {
        const int n = idx >> 7, k = idx & 127;
        const float v = W1[(k & 63) * 128 + n];
        img[n * SA + k] = bfbits(k < 64 ? v : bfres(v));
    }
    __syncthreads();
    {
        const uint32_t base = smem_u32(img) + (uint32_t)((wid * 32 + b_nofs) * SA + b_koff) * 2;
        for (int f = 0; f < 8; f++) {
            const int kimg = (f < 4) ? f * 16 : 64 + (f - 4) * 16;
            uint32_t r[4];
            ldsm_x4(r, base + kimg * 2);
            g_B1f[net][wid][f][0][lane] = make_uint4(r[0], r[1], r[2], r[3]);
            ldsm_x4(r, base + kimg * 2 + 16 * SA * 2);
            g_B1f[net][wid][f][1][lane] = make_uint4(r[0], r[1], r[2], r[3]);
        }
    }
    __syncthreads();

    // ---- B2 image: rows n 0..31, cols k 0..255 (k<128 hi, else lo), stride 264
    for (int idx = tid; idx < 32 * 256; idx += 128) {
        const int n = idx >> 8, k = idx & 255;
        const float v = W2[(k & 127) * 32 + n];
        img[n * 264 + k] = bfbits(k < 128 ? v : bfres(v));
    }
    __syncthreads();
    {
        const int l = lane & 15;
        const uint32_t base = smem_u32(img)
            + (uint32_t)((wid * 8 + (l & 7)) * 264 + (((l >> 3) & 1) << 3)) * 2;
        for (int f = 0; f < 16; f++) {
            const int kimg = (f < 8) ? f * 16 : 128 + (f - 8) * 16;
            uint32_t r[2];
            ldsm_x2(r, base + kimg * 2);
            g_B2f[net][wid][f][lane] = make_uint2(r[0], r[1]);
        }
    }
    __syncthreads();

    // ---- X image: rows n 0..127, cols 0..15 WXhi, 16..31 WXlo, 32=b1_hi 33=b1_lo
    for (int idx = tid; idx < 128 * 48; idx += 128) {
        const int n = idx / 48, k = idx % 48;
        float v = 0.0f;
        if (k < 16)       v = W1[(64 + k) * 128 + n];
        else if (k < 32)  v = bfres(W1[(64 + k - 16) * 128 + n]);
        else if (k == 32) v = b1[n];
        else if (k == 33) v = bfres(b1[n]);
        img[n * 56 + k] = bfbits(v);
    }
    __syncthreads();
    {
        const uint32_t base = smem_u32(img) + (uint32_t)((wid * 32 + b_nofs) * 56 + b_koff) * 2;
        for (int f = 0; f < 3; f++) {
            uint32_t r[4];
            ldsm_x4(r, base + f * 16 * 2);
            g_BXf[net][wid][f][0][lane] = make_uint4(r[0], r[1], r[2], r[3]);
            ldsm_x4(r, base + f * 16 * 2 + 16 * 56 * 2);
            g_BXf[net][wid][f][1][lane] = make_uint4(r[0], r[1], r[2], r[3]);
        }
    }
}

// ---------------------------------------------------------------------------
// One integrator phase.  256 threads, 64 nodes/block, 4 blocks/SM.
// ---------------------------------------------------------------------------
__global__ __launch_bounds__(NTHR, 4)
void tc_phase(float* __restrict__ state, const float* __restrict__ tfinal,
              const float* __restrict__ b2, const int* __restrict__ nbrs,
              int net, int roff, int woff, float t_base, float dt_max)
{
    extern __shared__ unsigned char smx[];
    const uint32_t sbase = smem_u32(smx);
    const int tid = threadIdx.x;
    const int wid = tid >> 5;
    const int lane = tid & 31;
    const int mblk = blockIdx.x;
    const int m0 = mblk * TMN;

    // ---- build A1 [64 x 128]: cols 0..63 = x_hi (self|nbr), 64..127 = x_lo ----
    {
        const int r = tid >> 2, part = tid & 3;   // part 0/1: self halves; 2/3: nbr halves
        const int m = m0 + r;
        float z[16];
        if (part < 2) {
            const float* p = state + (size_t)m * 80 + roff + part * 16;
            #pragma unroll
            for (int i = 0; i < 4; i++) {
                float4 v = ((const float4*)p)[i];
                z[4*i] = v.x; z[4*i+1] = v.y; z[4*i+2] = v.z; z[4*i+3] = v.w;
            }
        } else {
            const int b = m >> 12, n = m & (NN - 1);
            const int4 nb = *(const int4*)(nbrs + n * 4);
            const int nbase = b << 12;
            const int off = roff + (part - 2) * 16;
            const float* p0 = state + (size_t)(nbase + nb.x) * 80 + off;
            const float* p1 = state + (size_t)(nbase + nb.y) * 80 + off;
            const float* p2 = state + (size_t)(nbase + nb.z) * 80 + off;
            const float* p3 = state + (size_t)(nbase + nb.w) * 80 + off;
            #pragma unroll
            for (int i = 0; i < 4; i++) {
                float4 a0 = ((const float4*)p0)[i], a1 = ((const float4*)p1)[i];
                float4 a2 = ((const float4*)p2)[i], a3 = ((const float4*)p3)[i];
                z[4*i]   = 0.25f * ((a0.x + a1.x) + (a2.x + a3.x));
                z[4*i+1] = 0.25f * ((a0.y + a1.y) + (a2.y + a3.y));
                z[4*i+2] = 0.25f * ((a0.z + a1.z) + (a2.z + a3.z));
                z[4*i+3] = 0.25f * ((a0.w + a1.w) + (a2.w + a3.w));
            }
        }
        const int c0 = part * 16;
        // vectorized: 4x STS.128 per thread (hi pair + lo pair), conflict-schedulable
        uint4 h0 = make_uint4(bfhi2(z[0],z[1]),  bfhi2(z[2],z[3]),
                              bfhi2(z[4],z[5]),  bfhi2(z[6],z[7]));
        uint4 h1 = make_uint4(bfhi2(z[8],z[9]),  bfhi2(z[10],z[11]),
                              bfhi2(z[12],z[13]),bfhi2(z[14],z[15]));
        uint4 l0 = make_uint4(bfhi2(bfres(z[0]),bfres(z[1])),  bfhi2(bfres(z[2]),bfres(z[3])),
                              bfhi2(bfres(z[4]),bfres(z[5])),  bfhi2(bfres(z[6]),bfres(z[7])));
        uint4 l1 = make_uint4(bfhi2(bfres(z[8]),bfres(z[9])),  bfhi2(bfres(z[10]),bfres(z[11])),
                              bfhi2(bfres(z[12]),bfres(z[13])),bfhi2(bfres(z[14]),bfres(z[15])));
        *(uint4*)(smx + SM_A1 + (r * SA + c0) * 2)          = h0;
        *(uint4*)(smx + SM_A1 + (r * SA + c0 + 8) * 2)      = h1;
        *(uint4*)(smx + SM_A1 + (r * SA + 64 + c0) * 2)     = l0;
        *(uint4*)(smx + SM_A1 + (r * SA + 64 + c0 + 8) * 2) = l1;
    }

    const int a_row  = lane & 15;
    const int a_koff = (lane >> 4) << 3;
    const int wmI = wid >> 2, wnI = wid & 3;
    const int wm = wmI * 32;
    const int wn = wnI * 32;

    // ---- xi + bias k-steps (global fragments only -> before the barrier) ----
    float acc[2][4][4];
    #pragma unroll
    for (int mi = 0; mi < 2; mi++)
        #pragma unroll
        for (int nj = 0; nj < 4; nj++)
            #pragma unroll
            for (int e = 0; e < 4; e++) acc[mi][nj][e] = 0.0f;

    {
        const int g = mblk * 2 + wmI;
        uint32_t aH[2][4], aL[2][4];
        #pragma unroll
        for (int mi = 0; mi < 2; mi++) {
            const uint4 vh = __ldg(&g_XIf[g][0][mi][lane]);
            aH[mi][0] = vh.x; aH[mi][1] = vh.y; aH[mi][2] = vh.z; aH[mi][3] = vh.w;
            const uint4 vl = __ldg(&g_XIf[g][1][mi][lane]);
            aL[mi][0] = vl.x; aL[mi][1] = vl.y; aL[mi][2] = vl.z; aL[mi][3] = vl.w;
        }
        {   // xiH @ WXhi ; xiL @ WXhi
            const uint4 b0 = __ldg(&g_BXf[net][wnI][0][0][lane]);
            const uint4 b1v = __ldg(&g_BXf[net][wnI][0][1][lane]);
            #pragma unroll
            for (int mi = 0; mi < 2; mi++) {
                mma16816(acc[mi][0], aH[mi], b0.x, b0.y);
                mma16816(acc[mi][1], aH[mi], b0.z, b0.w);
                mma16816(acc[mi][2], aH[mi], b1v.x, b1v.y);
                mma16816(acc[mi][3], aH[mi], b1v.z, b1v.w);
                mma16816(acc[mi][0], aL[mi], b0.x, b0.y);
                mma16816(acc[mi][1], aL[mi], b0.z, b0.w);
                mma16816(acc[mi][2], aL[mi], b1v.x, b1v.y);
                mma16816(acc[mi][3], aL[mi], b1v.z, b1v.w);
            }
        }
        {   // xiH @ WXlo
            const uint4 b0 = __ldg(&g_BXf[net][wnI][1][0][lane]);
            const uint4 b1v = __ldg(&g_BXf[net][wnI][1][1][lane]);
            #pragma unroll
            for (int mi = 0; mi < 2; mi++) {
                mma16816(acc[mi][0], aH[mi], b0.x, b0.y);
                mma16816(acc[mi][1], aH[mi], b0.z, b0.w);
                mma16816(acc[mi][2], aH[mi], b1v.x, b1v.y);
                mma16816(acc[mi][3], aH[mi], b1v.z, b1v.w);
            }
        }
        {   // bias: A cols 0,1 = 1.0 (inline)
            uint32_t aBias[4];
            const uint32_t one2 = ((lane & 3) == 0) ? 0x3F803F80u : 0u;
            aBias[0] = one2; aBias[1] = one2; aBias[2] = 0u; aBias[3] = 0u;
            const uint4 b0 = __ldg(&g_BXf[net][wnI][2][0][lane]);
            const uint4 b1v = __ldg(&g_BXf[net][wnI][2][1][lane]);
            #pragma unroll
            for (int mi = 0; mi < 2; mi++) {
                mma16816(acc[mi][0], aBias, b0.x, b0.y);
                mma16816(acc[mi][1], aBias, b0.z, b0.w);
                mma16816(acc[mi][2], aBias, b1v.x, b1v.y);
                mma16816(acc[mi][3], aBias, b1v.z, b1v.w);
            }
        }
    }
    __syncthreads();

    const uint32_t aB = sbase + SM_A1 + (uint32_t)((wm + a_row) * SA + a_koff) * 2;

    // ---- GEMM1: x_hi@W_hi + x_hi@W_lo, then x_lo@W_hi ----
    #pragma unroll
    for (int ks = 0; ks < 4; ks++) {
        uint32_t af[2][4];
        ldsm_x4(af[0], aB + ks * 32);
        ldsm_x4(af[1], aB + ks * 32 + 16 * SA * 2);
        {
            const uint4 b0 = __ldg(&g_B1f[net][wnI][ks][0][lane]);
            const uint4 b1v = __ldg(&g_B1f[net][wnI][ks][1][lane]);
            #pragma unroll
            for (int mi = 0; mi < 2; mi++) {
                mma16816(acc[mi][0], af[mi], b0.x, b0.y);
                mma16816(acc[mi][1], af[mi], b0.z, b0.w);
                mma16816(acc[mi][2], af[mi], b1v.x, b1v.y);
                mma16816(acc[mi][3], af[mi], b1v.z, b1v.w);
            }
        }
        {
            const uint4 b0 = __ldg(&g_B1f[net][wnI][4 + ks][0][lane]);
            const uint4 b1v = __ldg(&g_B1f[net][wnI][4 + ks][1][lane]);
            #pragma unroll
            for (int mi = 0; mi < 2; mi++) {
                mma16816(acc[mi][0], af[mi], b0.x, b0.y);
                mma16816(acc[mi][1], af[mi], b0.z, b0.w);
                mma16816(acc[mi][2], af[mi], b1v.x, b1v.y);
                mma16816(acc[mi][3], af[mi], b1v.z, b1v.w);
            }
        }
    }
    #pragma unroll
    for (int ks = 0; ks < 4; ks++) {
        uint32_t af[2][4];
        ldsm_x4(af[0], aB + (64 + ks * 16) * 2);
        ldsm_x4(af[1], aB + (64 + ks * 16) * 2 + 16 * SA * 2);
        const uint4 b0 = __ldg(&g_B1f[net][wnI][ks][0][lane]);
        const uint4 b1v = __ldg(&g_B1f[net][wnI][ks][1][lane]);
        #pragma unroll
        for (int mi = 0; mi < 2; mi++) {
            mma16816(acc[mi][0], af[mi], b0.x, b0.y);
            mma16816(acc[mi][1], af[mi], b0.z, b0.w);
            mma16816(acc[mi][2], af[mi], b1v.x, b1v.y);
            mma16816(acc[mi][3], af[mi], b1v.z, b1v.w);
        }
    }

    // ---- tanh -> h_hi / h_lo (separate 272B-stride arrays, conflict-free STS) ----
    {
        const int rb = wm + (lane >> 2);
        const int cbs = wn + (lane & 3) * 2;
        #pragma unroll
        for (int mi = 0; mi < 2; mi++) {
            #pragma unroll
            for (int nj = 0; nj < 4; nj++) {
                const int c = cbs + nj * 8;
                #pragma unroll
                for (int hh = 0; hh < 2; hh++) {
                    const int r = rb + mi * 16 + hh * 8;
                    const float t0 = fast_tanh(acc[mi][nj][hh * 2 + 0]);
                    const float t1 = fast_tanh(acc[mi][nj][hh * 2 + 1]);
                    *(uint32_t*)(smx + SM_HH + (r * SA + c) * 2) = bfhi2(t0, t1);
                    *(uint32_t*)(smx + SM_HL + (r * SA + c) * 2) = bfhi2(bfres(t0), bfres(t1));
                }
            }
        }
    }
    __syncthreads();

    // ---- GEMM2: h_hi@W2_hi + h_hi@W2_lo + h_lo@W2_hi ----
    const int wn2 = wnI * 8;
    float acc2[2][4];
    #pragma unroll
    for (int mi = 0; mi < 2; mi++)
        #pragma unroll
        for (int e = 0; e < 4; e++) acc2[mi][e] = 0.0f;

    const uint32_t hHB = sbase + SM_HH + (uint32_t)((wm + a_row) * SA + a_koff) * 2;
    const uint32_t hLB = sbase + SM_HL + (uint32_t)((wm + a_row) * SA + a_koff) * 2;
    #pragma unroll
    for (int ks = 0; ks < 8; ks++) {
        uint32_t af[2][4];
        ldsm_x4(af[0], hHB + ks * 32);
        ldsm_x4(af[1], hHB + ks * 32 + 16 * SA * 2);
        const uint2 bh = __ldg(&g_B2f[net][wnI][ks][lane]);
        const uint2 bl = __ldg(&g_B2f[net][wnI][8 + ks][lane]);
        mma16816(acc2[0], af[0], bh.x, bh.y);
        mma16816(acc2[1], af[1], bh.x, bh.y);
        mma16816(acc2[0], af[0], bl.x, bl.y);
        mma16816(acc2[1], af[1], bl.x, bl.y);
    }
    #pragma unroll
    for (int ks = 0; ks < 8; ks++) {
        uint32_t af[2][4];
        ldsm_x4(af[0], hLB + ks * 32);
        ldsm_x4(af[1], hLB + ks * 32 + 16 * SA * 2);
        const uint2 bh = __ldg(&g_B2f[net][wnI][ks][lane]);
        mma16816(acc2[0], af[0], bh.x, bh.y);
        mma16816(acc2[1], af[1], bh.x, bh.y);
    }

    // ---- epilogue: state += dt * (C2 + b2) ----
    {
        const float tf = __ldg(tfinal + (m0 >> 12));
        const float dt = fminf(fmaxf(tf - t_base, 0.0f), dt_max);
        const int c0 = wn2 + (lane & 3) * 2;
        const float b2v0 = __ldg(b2 + c0);
        const float b2v1 = __ldg(b2 + c0 + 1);
        #pragma unroll
        for (int mi = 0; mi < 2; mi++) {
            const int r0 = m0 + wm + mi * 16 + (lane >> 2);
            float* p0 = state + (size_t)r0 * 80 + woff + c0;
            p0[0] = fmaf(dt, acc2[mi][0] + b2v0, p0[0]);
            p0[1] = fmaf(dt, acc2[mi][1] + b2v1, p0[1]);
            float* p1 = state + (size_t)(r0 + 8) * 80 + woff + c0;
            p1[0] = fmaf(dt, acc2[mi][2] + b2v0, p1[0]);
            p1[1] = fmaf(dt, acc2[mi][3] + b2v1, p1[1]);
        }
    }
}

// ---------------------------------------------------------------------------
extern "C" void kernel_launch(void* const* d_in, const int* in_sizes, int n_in,
                              void* d_out, int out_size)
{
    const float* x   = (const float*)d_in[0];
    const float* tfi = (const float*)d_in[1];
    const float* W1q = (const float*)d_in[2];
    const float* b1q = (const float*)d_in[3];
    const float* W2q = (const float*)d_in[4];
    const float* b2q = (const float*)d_in[5];
    const float* W1p = (const float*)d_in[6];
    const float* b1p = (const float*)d_in[7];
    const float* W2p = (const float*)d_in[8];
    const float* b2p = (const float*)d_in[9];
    const int*  nbrs = (const int*)d_in[10];
    float* out = (float*)d_out;

    cudaFuncSetAttribute(tc_phase, cudaFuncAttributeMaxDynamicSharedMemorySize, SM_TOTAL);

    cudaMemcpyAsync(out, x, (size_t)NODES * 80 * sizeof(float),
                    cudaMemcpyDeviceToDevice);
    prep_xifrag<<<NODES / 128, 128>>>(x);
    prep_bfrag<<<2, 128>>>(W1q, b1q, W2q, W1p, b1p, W2p);

    float tq = 0.0f, tp = 0.0f;
    for (int k = 0; k < N_STEPS; k++) {
        const float rho = (k == 0) ? 0.5f : 1.0f;
        // q-update: reads p (offset 32), writes q (offset 0)
        tc_phase<<<NBLK, NTHR, SM_TOTAL>>>(out, tfi, b2q, nbrs, 0, POFF, 0, tq, rho * DT_STEP);
        tq += rho * DT_STEP;
        // p-update: reads q (offset 0), writes p (offset 32)
        tc_phase<<<NBLK, NTHR, SM_TOTAL>>>(out, tfi, b2p, nbrs, 1, 0, POFF, tp, DT_STEP);
        tp += DT_STEP;
    }
}